// round 6
// baseline (speedup 1.0000x reference)
#include <cuda_runtime.h>
#include <cuda_bf16.h>

#define HD    1024
#define SLEN  256
#define TLEN  256
#define VOUT  32000
#define G4    4096
#define NCTA_REC 128
#define STEPS 512

// ---------------- device scratch ----------------
__device__ __nv_bfloat16 g_linw_bf[(size_t)VOUT * HD];   // 65.5 MB
__device__ __nv_bfloat16 g_wih_bf[2ul * G4 * HD];        // 16.8 MB
__device__ __nv_bfloat16 g_xbf[(size_t)STEPS * HD];      // 1 MB
__device__ float         g_G[2ul * SLEN * G4];           // 8 MB
__device__ __nv_bfloat16 g_Hbf[(size_t)TLEN * HD];       // 0.5 MB
// h slots: {tag:u32 (hi), h_bits:u32 (lo)} per hidden unit, 2 parity buffers.
// Tag is self-certifying (travels with the data in one atomic 64-bit word),
// so relaxed loads/stores suffice -- no acquire/release needed.
__device__ unsigned long long g_hslot[2][HD];            // 16 KB

// ---------------- helpers ----------------
__device__ __forceinline__ void ffma2(unsigned long long &d,
                                      unsigned long long a, unsigned long long b) {
    asm("fma.rn.f32x2 %0, %1, %2, %0;" : "+l"(d) : "l"(a), "l"(b));
}
__device__ __forceinline__ void unpack2(unsigned long long v, float &lo, float &hi) {
    unsigned l, h;
    asm("mov.b64 {%0, %1}, %2;" : "=r"(l), "=r"(h) : "l"(v));
    lo = __uint_as_float(l); hi = __uint_as_float(h);
}
__device__ __forceinline__ unsigned long long ld_rlx64(const unsigned long long* p) {
    unsigned long long v;
    asm volatile("ld.relaxed.gpu.global.b64 %0, [%1];" : "=l"(v) : "l"(p) : "memory");
    return v;
}
__device__ __forceinline__ void st_rlx64(unsigned long long* p, unsigned long long v) {
    asm volatile("st.relaxed.gpu.global.b64 [%0], %1;" :: "l"(p), "l"(v) : "memory");
}
__device__ __forceinline__ float tanh_hw(float x) {
    float y;
    asm("tanh.approx.f32 %0, %1;" : "=f"(y) : "f"(x));
    return y;
}
__device__ __forceinline__ float sig_hw(float x) {
    return fmaf(tanh_hw(0.5f * x), 0.5f, 0.5f);
}
__device__ __forceinline__ void mma_bf16(float c[4],
                                         unsigned a0, unsigned a1, unsigned a2, unsigned a3,
                                         unsigned b0, unsigned b1) {
    asm volatile("mma.sync.aligned.m16n8k16.row.col.f32.bf16.bf16.f32 "
                 "{%0,%1,%2,%3}, {%4,%5,%6,%7}, {%8,%9}, {%0,%1,%2,%3};"
                 : "+f"(c[0]), "+f"(c[1]), "+f"(c[2]), "+f"(c[3])
                 : "r"(a0), "r"(a1), "r"(a2), "r"(a3), "r"(b0), "r"(b1));
}

// ---------------- 1) embedding gather (f32 -> bf16) ----------------
__global__ void embed_kernel(const int* __restrict__ src, const int* __restrict__ trg,
                             const int* __restrict__ start,
                             const float* __restrict__ enc_emb,
                             const float* __restrict__ dec_emb) {
    const int t = blockIdx.x;           // 0..511
    const int tid = threadIdx.x;        // 256
    const float* emb; int tok;
    if (t < SLEN) { tok = src[t]; emb = enc_emb; }
    else {
        int tt = t - SLEN;
        tok = (tt == 0) ? start[0] : trg[tt - 1];
        emb = dec_emb;
    }
    const float4 v = ((const float4*)(emb + (size_t)tok * HD))[tid];
    __nv_bfloat162 p0 = __floats2bfloat162_rn(v.x, v.y);
    __nv_bfloat162 p1 = __floats2bfloat162_rn(v.z, v.w);
    __nv_bfloat162* d = (__nv_bfloat162*)(g_xbf + (size_t)t * HD);
    d[2 * tid]     = p0;
    d[2 * tid + 1] = p1;
}

// ---------------- 2) weight conversion + h-slot re-arm ----------------
__global__ void convert_kernel(const float* __restrict__ encWih,
                               const float* __restrict__ decWih,
                               const float* __restrict__ linW) {
    size_t i = (size_t)blockIdx.x * blockDim.x + threadIdx.x;
    size_t stride = (size_t)gridDim.x * blockDim.x;
    // re-arm every launch/replay: tag=0, h=0.0 in both parity buffers.
    unsigned long long* slots = (unsigned long long*)g_hslot;
    for (size_t j = i; j < 2 * HD; j += stride) slots[j] = 0ull;
    const size_t NW = (size_t)G4 * HD;
    for (size_t j = i; j < NW; j += stride) {
        g_wih_bf[j]      = __float2bfloat16(encWih[j]);
        g_wih_bf[NW + j] = __float2bfloat16(decWih[j]);
    }
    const size_t NL = (size_t)VOUT * HD;
    for (size_t j = i; j < NL; j += stride) g_linw_bf[j] = __float2bfloat16(linW[j]);
}

// ---------------- 3) G = X @ Wih^T + (bih+bhh), tensor cores ----------------
__global__ void __launch_bounds__(128) wx_mma(const float* __restrict__ eb_ih,
                                              const float* __restrict__ eb_hh,
                                              const float* __restrict__ db_ih,
                                              const float* __restrict__ db_hh) {
    const int net = blockIdx.z;
    const __nv_bfloat16* A = g_wih_bf + (size_t)net * G4 * HD;
    const __nv_bfloat16* B = g_xbf + (size_t)net * SLEN * HD;
    const float* bih = net ? db_ih : eb_ih;
    const float* bhh = net ? db_hh : eb_hh;
    float* Gout = g_G + (size_t)net * SLEN * G4;

    const int tid = threadIdx.x;
    const int w = tid >> 5, lane = tid & 31;
    const int group = lane >> 2, tig = lane & 3;
    const int bm = blockIdx.x * 128 + w * 32;
    const int bn = blockIdx.y * 64;

    float acc[2][8][4];
    #pragma unroll
    for (int mf = 0; mf < 2; mf++)
        #pragma unroll
        for (int nf = 0; nf < 8; nf++)
            #pragma unroll
            for (int q = 0; q < 4; q++) acc[mf][nf][q] = 0.f;

    for (int k0 = 0; k0 < HD; k0 += 16) {
        unsigned a[2][4], b[8][2];
        #pragma unroll
        for (int mf = 0; mf < 2; mf++) {
            const __nv_bfloat16* ab = A + (size_t)(bm + mf * 16 + group) * HD + k0 + 2 * tig;
            a[mf][0] = *(const unsigned*)(ab);
            a[mf][1] = *(const unsigned*)(ab + 8 * HD);
            a[mf][2] = *(const unsigned*)(ab + 8);
            a[mf][3] = *(const unsigned*)(ab + 8 * HD + 8);
        }
        #pragma unroll
        for (int nf = 0; nf < 8; nf++) {
            const __nv_bfloat16* bb = B + (size_t)(bn + nf * 8 + group) * HD + k0 + 2 * tig;
            b[nf][0] = *(const unsigned*)(bb);
            b[nf][1] = *(const unsigned*)(bb + 8);
        }
        #pragma unroll
        for (int mf = 0; mf < 2; mf++)
            #pragma unroll
            for (int nf = 0; nf < 8; nf++)
                mma_bf16(acc[mf][nf], a[mf][0], a[mf][1], a[mf][2], a[mf][3],
                         b[nf][0], b[nf][1]);
    }
    #pragma unroll
    for (int mf = 0; mf < 2; mf++) {
        const int m0 = bm + mf * 16 + group;
        const float bias0 = bih[m0] + bhh[m0];
        const float bias8 = bih[m0 + 8] + bhh[m0 + 8];
        #pragma unroll
        for (int nf = 0; nf < 8; nf++) {
            const int n = bn + nf * 8 + 2 * tig;
            Gout[(size_t)n * G4 + m0]           = acc[mf][nf][0] + bias0;
            Gout[(size_t)(n + 1) * G4 + m0]     = acc[mf][nf][1] + bias0;
            Gout[(size_t)n * G4 + m0 + 8]       = acc[mf][nf][2] + bias8;
            Gout[(size_t)(n + 1) * G4 + m0 + 8] = acc[mf][nf][3] + bias8;
        }
    }
}

// ---------------- 4) persistent LSTM recurrence (warp-autonomous units) ----------------
// Warp w of CTA c owns hidden unit (8c + w): it computes all 4 gate rows of that
// unit (global rows q*1024 + unit, q = i,f,g,o), reduces intra-warp, and lane 0
// runs the cell and publishes the tagged slot. No cross-warp exchange per step.
__device__ __forceinline__ void load_w(ulonglong2 (&wv)[4][8], const float* __restrict__ W,
                                       int unit, int lane) {
    #pragma unroll
    for (int q = 0; q < 4; q++) {
        const float* row = W + (size_t)(q * HD + unit) * HD + lane * 4;
        #pragma unroll
        for (int c = 0; c < 8; c++)
            wv[q][c] = *(const ulonglong2*)(row + c * 128);
    }
}

__global__ void __launch_bounds__(256, 1) rec_kernel(const float* __restrict__ encWhh,
                                                     const float* __restrict__ decWhh) {
    extern __shared__ float sm[];
    float* gsl = sm;                 // [512][32] precomputed Wx+bias gates (r = q*8+u)
    float* h_s = gsl + STEPS * 32;   // [2][1024] parity-buffered h staging

    const int tid = threadIdx.x, cta = blockIdx.x;
    const int w = tid >> 5, lane = tid & 31;
    const int base = cta * 8;
    const int unit = base + w;

    // preload this CTA's G slice for all 512 steps (64 KB)
    for (int i = tid; i < STEPS * 32; i += 256) {
        const int s = i >> 5, r = i & 31, q = r >> 3, u = r & 7;
        gsl[i] = g_G[(size_t)(s >> 8) * SLEN * G4 + (size_t)(s & 255) * G4 + q * HD + base + u];
    }

    // encoder Whh rows of this warp's unit -> registers (f32, 128 regs)
    ulonglong2 wv[4][8];
    load_w(wv, encWhh, unit, lane);

    float cstate = 0.f;     // live in lane 0 only
    __syncthreads();        // gsl ready

    for (int t = 0; t < STEPS; t++) {
        if (t == SLEN) load_w(wv, decWhh, unit, lane);   // phase switch

        // ---- poll own 4 slots with RELAXED loads (tags are self-certifying,
        //      all 4 loads pipeline into ~one L2 round per iteration) ----
        const unsigned long long* sp = g_hslot[t & 1] + 4 * tid;
        const unsigned tw = (unsigned)t;
        unsigned long long s0, s1, s2, s3;
        for (;;) {
            s0 = ld_rlx64(sp);
            s1 = ld_rlx64(sp + 1);
            s2 = ld_rlx64(sp + 2);
            s3 = ld_rlx64(sp + 3);
            if ((((unsigned)(s0 >> 32)) == tw) & (((unsigned)(s1 >> 32)) == tw) &
                (((unsigned)(s2 >> 32)) == tw) & (((unsigned)(s3 >> 32)) == tw)) break;
        }
        float* hp = h_s + (t & 1) * HD;
        float4 hvv;
        hvv.x = __uint_as_float((unsigned)s0);
        hvv.y = __uint_as_float((unsigned)s1);
        hvv.z = __uint_as_float((unsigned)s2);
        hvv.w = __uint_as_float((unsigned)s3);
        ((float4*)hp)[tid] = hvv;
        __syncthreads();    // the only barrier per step

        // ---- 4 gate rows of this warp's unit (packed f32x2 FMA) ----
        unsigned long long acc2[4] = {0ull, 0ull, 0ull, 0ull};
        #pragma unroll
        for (int c = 0; c < 8; c++) {
            const ulonglong2 hv = *(const ulonglong2*)(hp + lane * 4 + c * 128);
            #pragma unroll
            for (int q = 0; q < 4; q++) {
                ffma2(acc2[q], wv[q][c].x, hv.x);
                ffma2(acc2[q], wv[q][c].y, hv.y);
            }
        }
        float accf[4];
        #pragma unroll
        for (int q = 0; q < 4; q++) {
            float lo, hi; unpack2(acc2[q], lo, hi);
            accf[q] = lo + hi;
        }
        #pragma unroll
        for (int off = 16; off; off >>= 1) {
            #pragma unroll
            for (int q = 0; q < 4; q++)
                accf[q] += __shfl_xor_sync(0xffffffffu, accf[q], off);
        }

        // ---- cell on lane 0: HW tanh, publish tagged slot ----
        if (lane == 0) {
            const float* gx = gsl + t * 32;
            const float gi = accf[0] + gx[w];
            const float gf = accf[1] + gx[8 + w];
            const float gg = accf[2] + gx[16 + w];
            const float go = accf[3] + gx[24 + w];
            const float iv = sig_hw(gi), fv = sig_hw(gf);
            const float gv = tanh_hw(gg), ov = sig_hw(go);
            cstate = fv * cstate + iv * gv;
            const float hh = ov * tanh_hw(cstate);
            const unsigned long long slot =
                ((unsigned long long)(unsigned)(t + 1) << 32) |
                (unsigned long long)__float_as_uint(hh);
            st_rlx64(&g_hslot[(t + 1) & 1][unit], slot);
            if (t >= SLEN) g_Hbf[(size_t)(t - SLEN) * HD + unit] = __float2bfloat16(hh);
        }
        // warps roll independently into the next poll; parity-buffered h_s and
        // the per-step barrier bound the intra-CTA skew to one step.
    }
}

// ---------------- 5) logits = H @ linW^T + lin_b, tensor cores ----------------
__global__ void __launch_bounds__(128) logits_mma(const float* __restrict__ lin_b,
                                                  float* __restrict__ out) {
    const int tid = threadIdx.x;
    const int w = tid >> 5, lane = tid & 31;
    const int group = lane >> 2, tig = lane & 3;
    const size_t bm = (size_t)blockIdx.x * 128 + w * 32;
    const int bn = blockIdx.y * 64;

    float acc[2][8][4];
    #pragma unroll
    for (int mf = 0; mf < 2; mf++)
        #pragma unroll
        for (int nf = 0; nf < 8; nf++)
            #pragma unroll
            for (int q = 0; q < 4; q++) acc[mf][nf][q] = 0.f;

    for (int k0 = 0; k0 < HD; k0 += 16) {
        unsigned a[2][4], b[8][2];
        #pragma unroll
        for (int mf = 0; mf < 2; mf++) {
            const __nv_bfloat16* ab = g_linw_bf + (bm + mf * 16 + group) * HD + k0 + 2 * tig;
            a[mf][0] = *(const unsigned*)(ab);
            a[mf][1] = *(const unsigned*)(ab + 8 * HD);
            a[mf][2] = *(const unsigned*)(ab + 8);
            a[mf][3] = *(const unsigned*)(ab + 8 * HD + 8);
        }
        #pragma unroll
        for (int nf = 0; nf < 8; nf++) {
            const __nv_bfloat16* bb = g_Hbf + (size_t)(bn + nf * 8 + group) * HD + k0 + 2 * tig;
            b[nf][0] = *(const unsigned*)(bb);
            b[nf][1] = *(const unsigned*)(bb + 8);
        }
        #pragma unroll
        for (int mf = 0; mf < 2; mf++)
            #pragma unroll
            for (int nf = 0; nf < 8; nf++)
                mma_bf16(acc[mf][nf], a[mf][0], a[mf][1], a[mf][2], a[mf][3],
                         b[nf][0], b[nf][1]);
    }
    #pragma unroll
    for (int mf = 0; mf < 2; mf++) {
        const size_t m0 = bm + mf * 16 + group;
        const float bias0 = lin_b[m0];
        const float bias8 = lin_b[m0 + 8];
        #pragma unroll
        for (int nf = 0; nf < 8; nf++) {
            const int n = bn + nf * 8 + 2 * tig;
            out[(size_t)n * VOUT + m0]           = acc[mf][nf][0] + bias0;
            out[(size_t)(n + 1) * VOUT + m0]     = acc[mf][nf][1] + bias0;
            out[(size_t)n * VOUT + m0 + 8]       = acc[mf][nf][2] + bias8;
            out[(size_t)(n + 1) * VOUT + m0 + 8] = acc[mf][nf][3] + bias8;
        }
    }
}

// ---------------- 6) in-place row log_softmax (online) ----------------
__global__ void __launch_bounds__(256) logsoftmax_kernel(float* __restrict__ out) {
    const int t = blockIdx.x;
    float* row = out + (size_t)t * VOUT;
    const int tid = threadIdx.x;
    __shared__ float smx[8], ssm[8];
    __shared__ float sbcast;

    float m = -3.4e38f, s = 0.f;
    for (int i = tid; i < VOUT; i += 256) {
        const float v = row[i];
        const float nm = fmaxf(m, v);
        s = s * __expf(m - nm) + __expf(v - nm);
        m = nm;
    }
    #pragma unroll
    for (int o = 16; o; o >>= 1) {
        const float mo = __shfl_xor_sync(0xffffffffu, m, o);
        const float so = __shfl_xor_sync(0xffffffffu, s, o);
        const float nm = fmaxf(m, mo);
        s = s * __expf(m - nm) + so * __expf(mo - nm);
        m = nm;
    }
    if ((tid & 31) == 0) { smx[tid >> 5] = m; ssm[tid >> 5] = s; }
    __syncthreads();
    if (tid == 0) {
        float M = smx[0], S = ssm[0];
        for (int wq = 1; wq < 8; wq++) {
            const float nm = fmaxf(M, smx[wq]);
            S = S * __expf(M - nm) + ssm[wq] * __expf(smx[wq] - nm);
            M = nm;
        }
        sbcast = M + logf(S);
    }
    __syncthreads();
    const float lse = sbcast;
    for (int i = tid; i < VOUT; i += 256) row[i] -= lse;
}

// ---------------- launch ----------------
extern "C" void kernel_launch(void* const* d_in, const int* in_sizes, int n_in,
                              void* d_out, int out_size) {
    const int*   src     = (const int*)d_in[0];
    const int*   trg     = (const int*)d_in[1];
    const int*   start   = (const int*)d_in[2];
    const float* enc_emb = (const float*)d_in[3];
    const float* enc_Wih = (const float*)d_in[4];
    const float* enc_Whh = (const float*)d_in[5];
    const float* enc_bih = (const float*)d_in[6];
    const float* enc_bhh = (const float*)d_in[7];
    const float* dec_emb = (const float*)d_in[8];
    const float* dec_Wih = (const float*)d_in[9];
    const float* dec_Whh = (const float*)d_in[10];
    const float* dec_bih = (const float*)d_in[11];
    const float* dec_bhh = (const float*)d_in[12];
    const float* lin_W   = (const float*)d_in[13];
    const float* lin_b   = (const float*)d_in[14];
    float* out = (float*)d_out;

    embed_kernel<<<STEPS, 256>>>(src, trg, start, enc_emb, dec_emb);
    convert_kernel<<<2048, 256>>>(enc_Wih, dec_Wih, lin_W);

    dim3 gwx(G4 / 128, SLEN / 64, 2);
    wx_mma<<<gwx, 128>>>(enc_bih, enc_bhh, dec_bih, dec_bhh);

    const int REC_SMEM = (STEPS * 32 + 2 * HD) * 4;   // ~73.7 KB
    cudaFuncSetAttribute(rec_kernel, cudaFuncAttributeMaxDynamicSharedMemorySize, REC_SMEM);
    rec_kernel<<<NCTA_REC, 256, REC_SMEM>>>(enc_Whh, dec_Whh);

    dim3 gl(VOUT / 128, TLEN / 64);
    logits_mma<<<gl, 128>>>(lin_b, out);

    logsoftmax_kernel<<<TLEN, 256>>>(out);
}

// round 7
// speedup vs baseline: 2.1132x; 2.1132x over previous
#include <cuda_runtime.h>
#include <cuda_bf16.h>

#define HD    1024
#define SLEN  256
#define TLEN  256
#define VOUT  32000
#define G4    4096
#define NCTA_REC 128
#define STEPS 512

// ---------------- device scratch ----------------
__device__ __nv_bfloat16 g_linw_bf[(size_t)VOUT * HD];   // 65.5 MB
__device__ __nv_bfloat16 g_wih_bf[2ul * G4 * HD];        // 16.8 MB
__device__ __nv_bfloat16 g_xbf[(size_t)STEPS * HD];      // 1 MB
__device__ float         g_G[2ul * SLEN * G4];           // 8 MB
__device__ __nv_bfloat16 g_Hbf[(size_t)TLEN * HD];       // 0.5 MB
// h slots: {tag:u32 (hi), h_bits:u32 (lo)} per hidden unit, 2 parity buffers.
// Tag travels with the data in one 64-bit word -> self-certifying -> relaxed ops.
__device__ unsigned long long g_hslot[2][HD];            // 16 KB

// ---------------- helpers ----------------
__device__ __forceinline__ void ffma2(unsigned long long &d,
                                      unsigned long long a, unsigned long long b) {
    asm("fma.rn.f32x2 %0, %1, %2, %0;" : "+l"(d) : "l"(a), "l"(b));
}
__device__ __forceinline__ void unpack2(unsigned long long v, float &lo, float &hi) {
    unsigned l, h;
    asm("mov.b64 {%0, %1}, %2;" : "=r"(l), "=r"(h) : "l"(v));
    lo = __uint_as_float(l); hi = __uint_as_float(h);
}
__device__ __forceinline__ unsigned long long ld_rlx64(const unsigned long long* p) {
    unsigned long long v;
    asm volatile("ld.relaxed.gpu.global.b64 %0, [%1];" : "=l"(v) : "l"(p) : "memory");
    return v;
}
__device__ __forceinline__ void st_rlx64(unsigned long long* p, unsigned long long v) {
    asm volatile("st.relaxed.gpu.global.b64 [%0], %1;" :: "l"(p), "l"(v) : "memory");
}
__device__ __forceinline__ float tanh_hw(float x) {
    float y;
    asm("tanh.approx.f32 %0, %1;" : "=f"(y) : "f"(x));
    return y;
}
__device__ __forceinline__ float sig_hw(float x) {
    return fmaf(tanh_hw(0.5f * x), 0.5f, 0.5f);
}
__device__ __forceinline__ void mma_bf16(float c[4],
                                         unsigned a0, unsigned a1, unsigned a2, unsigned a3,
                                         unsigned b0, unsigned b1) {
    asm volatile("mma.sync.aligned.m16n8k16.row.col.f32.bf16.bf16.f32 "
                 "{%0,%1,%2,%3}, {%4,%5,%6,%7}, {%8,%9}, {%0,%1,%2,%3};"
                 : "+f"(c[0]), "+f"(c[1]), "+f"(c[2]), "+f"(c[3])
                 : "r"(a0), "r"(a1), "r"(a2), "r"(a3), "r"(b0), "r"(b1));
}

// ---------------- 1) embedding gather (f32 -> bf16) ----------------
__global__ void embed_kernel(const int* __restrict__ src, const int* __restrict__ trg,
                             const int* __restrict__ start,
                             const float* __restrict__ enc_emb,
                             const float* __restrict__ dec_emb) {
    const int t = blockIdx.x;           // 0..511
    const int tid = threadIdx.x;        // 256
    const float* emb; int tok;
    if (t < SLEN) { tok = src[t]; emb = enc_emb; }
    else {
        int tt = t - SLEN;
        tok = (tt == 0) ? start[0] : trg[tt - 1];
        emb = dec_emb;
    }
    const float4 v = ((const float4*)(emb + (size_t)tok * HD))[tid];
    __nv_bfloat162 p0 = __floats2bfloat162_rn(v.x, v.y);
    __nv_bfloat162 p1 = __floats2bfloat162_rn(v.z, v.w);
    __nv_bfloat162* d = (__nv_bfloat162*)(g_xbf + (size_t)t * HD);
    d[2 * tid]     = p0;
    d[2 * tid + 1] = p1;
}

// ---------------- 2) weight conversion + h-slot re-arm ----------------
__global__ void convert_kernel(const float* __restrict__ encWih,
                               const float* __restrict__ decWih,
                               const float* __restrict__ linW) {
    size_t i = (size_t)blockIdx.x * blockDim.x + threadIdx.x;
    size_t stride = (size_t)gridDim.x * blockDim.x;
    // re-arm every launch/replay: tag=0, h=0.0 in both parity buffers.
    unsigned long long* slots = (unsigned long long*)g_hslot;
    for (size_t j = i; j < 2 * HD; j += stride) slots[j] = 0ull;
    const size_t NW = (size_t)G4 * HD;
    for (size_t j = i; j < NW; j += stride) {
        g_wih_bf[j]      = __float2bfloat16(encWih[j]);
        g_wih_bf[NW + j] = __float2bfloat16(decWih[j]);
    }
    const size_t NL = (size_t)VOUT * HD;
    for (size_t j = i; j < NL; j += stride) g_linw_bf[j] = __float2bfloat16(linW[j]);
}

// ---------------- 3) G = X @ Wih^T + (bih+bhh), tensor cores ----------------
__global__ void __launch_bounds__(128) wx_mma(const float* __restrict__ eb_ih,
                                              const float* __restrict__ eb_hh,
                                              const float* __restrict__ db_ih,
                                              const float* __restrict__ db_hh) {
    const int net = blockIdx.z;
    const __nv_bfloat16* A = g_wih_bf + (size_t)net * G4 * HD;
    const __nv_bfloat16* B = g_xbf + (size_t)net * SLEN * HD;
    const float* bih = net ? db_ih : eb_ih;
    const float* bhh = net ? db_hh : eb_hh;
    float* Gout = g_G + (size_t)net * SLEN * G4;

    const int tid = threadIdx.x;
    const int w = tid >> 5, lane = tid & 31;
    const int group = lane >> 2, tig = lane & 3;
    const int bm = blockIdx.x * 128 + w * 32;
    const int bn = blockIdx.y * 64;

    float acc[2][8][4];
    #pragma unroll
    for (int mf = 0; mf < 2; mf++)
        #pragma unroll
        for (int nf = 0; nf < 8; nf++)
            #pragma unroll
            for (int q = 0; q < 4; q++) acc[mf][nf][q] = 0.f;

    for (int k0 = 0; k0 < HD; k0 += 16) {
        unsigned a[2][4], b[8][2];
        #pragma unroll
        for (int mf = 0; mf < 2; mf++) {
            const __nv_bfloat16* ab = A + (size_t)(bm + mf * 16 + group) * HD + k0 + 2 * tig;
            a[mf][0] = *(const unsigned*)(ab);
            a[mf][1] = *(const unsigned*)(ab + 8 * HD);
            a[mf][2] = *(const unsigned*)(ab + 8);
            a[mf][3] = *(const unsigned*)(ab + 8 * HD + 8);
        }
        #pragma unroll
        for (int nf = 0; nf < 8; nf++) {
            const __nv_bfloat16* bb = B + (size_t)(bn + nf * 8 + group) * HD + k0 + 2 * tig;
            b[nf][0] = *(const unsigned*)(bb);
            b[nf][1] = *(const unsigned*)(bb + 8);
        }
        #pragma unroll
        for (int mf = 0; mf < 2; mf++)
            #pragma unroll
            for (int nf = 0; nf < 8; nf++)
                mma_bf16(acc[mf][nf], a[mf][0], a[mf][1], a[mf][2], a[mf][3],
                         b[nf][0], b[nf][1]);
    }
    #pragma unroll
    for (int mf = 0; mf < 2; mf++) {
        const int m0 = bm + mf * 16 + group;
        const float bias0 = bih[m0] + bhh[m0];
        const float bias8 = bih[m0 + 8] + bhh[m0 + 8];
        #pragma unroll
        for (int nf = 0; nf < 8; nf++) {
            const int n = bn + nf * 8 + 2 * tig;
            Gout[(size_t)n * G4 + m0]           = acc[mf][nf][0] + bias0;
            Gout[(size_t)(n + 1) * G4 + m0]     = acc[mf][nf][1] + bias0;
            Gout[(size_t)n * G4 + m0 + 8]       = acc[mf][nf][2] + bias8;
            Gout[(size_t)(n + 1) * G4 + m0 + 8] = acc[mf][nf][3] + bias8;
        }
    }
}

// ---------------- 4) persistent LSTM recurrence ----------------
// R2/R5 skeleton: warp w computes gate rows w*4..w*4+3 (r = q*8+u), gate exchange
// via smem, warp 0 runs all 8 cells gate-parallel and publishes 8 tagged slots
// from one instruction. Polls are RELAXED (R6-proven): 4 pipelined ld.relaxed.b64
// per iteration ~= one L2 round, tags self-certify the data.
__device__ __forceinline__ void load_w(ulonglong2 (&wv)[4][8], const float* __restrict__ W,
                                       int w, int lane, int base) {
    #pragma unroll
    for (int j = 0; j < 4; j++) {
        const int r = w * 4 + j, q = r >> 3, u = r & 7;
        const float* row = W + (size_t)(q * HD + base + u) * HD + lane * 4;
        #pragma unroll
        for (int c = 0; c < 8; c++)
            wv[j][c] = *(const ulonglong2*)(row + c * 128);
    }
}

__global__ void __launch_bounds__(256, 1) rec_kernel(const float* __restrict__ encWhh,
                                                     const float* __restrict__ decWhh) {
    extern __shared__ float sm[];
    float* gsl    = sm;                 // [512][32] precomputed Wx+bias gates (r = q*8+u)
    float* h_s    = gsl + STEPS * 32;   // [1024]
    float* gate_s = h_s + HD;           // [32]
    float* c_s    = gate_s + 32;        // [8]

    const int tid = threadIdx.x, cta = blockIdx.x;
    const int w = tid >> 5, lane = tid & 31;
    const int base = cta * 8;

    // preload this CTA's G slice for all 512 steps (64 KB)
    for (int i = tid; i < STEPS * 32; i += 256) {
        const int s = i >> 5, r = i & 31, q = r >> 3, u = r & 7;
        gsl[i] = g_G[(size_t)(s >> 8) * SLEN * G4 + (size_t)(s & 255) * G4 + q * HD + base + u];
    }

    // encoder Whh slice -> registers (f32, 128 regs)
    ulonglong2 wv[4][8];
    load_w(wv, encWhh, w, lane, base);

    if (tid < 8) c_s[tid] = 0.f;
    __syncthreads();    // gsl + c_s ready

    for (int t = 0; t < STEPS; t++) {
        if (t == SLEN) load_w(wv, decWhh, w, lane, base);   // phase switch

        // ---- relaxed poll of this thread's own 4 slots (one publisher CTA) ----
        const unsigned long long* sp = g_hslot[t & 1] + 4 * tid;
        const unsigned tw = (unsigned)t;
        unsigned long long s0, s1, s2, s3;
        for (;;) {
            s0 = ld_rlx64(sp);
            s1 = ld_rlx64(sp + 1);
            s2 = ld_rlx64(sp + 2);
            s3 = ld_rlx64(sp + 3);
            if ((((unsigned)(s0 >> 32)) == tw) & (((unsigned)(s1 >> 32)) == tw) &
                (((unsigned)(s2 >> 32)) == tw) & (((unsigned)(s3 >> 32)) == tw)) break;
        }
        float4 hvv;
        hvv.x = __uint_as_float((unsigned)s0);
        hvv.y = __uint_as_float((unsigned)s1);
        hvv.z = __uint_as_float((unsigned)s2);
        hvv.w = __uint_as_float((unsigned)s3);
        ((float4*)h_s)[tid] = hvv;
        __syncthreads();

        // ---- Whh @ h for this CTA's 32 gate rows (packed f32x2 FMA) ----
        unsigned long long acc2[4] = {0ull, 0ull, 0ull, 0ull};
        #pragma unroll
        for (int c = 0; c < 8; c++) {
            const ulonglong2 hv = *(const ulonglong2*)(h_s + lane * 4 + c * 128);
            #pragma unroll
            for (int j = 0; j < 4; j++) {
                ffma2(acc2[j], wv[j][c].x, hv.x);
                ffma2(acc2[j], wv[j][c].y, hv.y);
            }
        }
        float accf[4];
        #pragma unroll
        for (int j = 0; j < 4; j++) {
            float lo, hi; unpack2(acc2[j], lo, hi);
            accf[j] = lo + hi;
        }
        #pragma unroll
        for (int off = 16; off; off >>= 1) {
            #pragma unroll
            for (int j = 0; j < 4; j++)
                accf[j] += __shfl_xor_sync(0xffffffffu, accf[j], off);
        }
        if (lane < 4) gate_s[w * 4 + lane] = accf[lane];
        __syncthreads();

        // ---- LSTM cell in warp 0: 32 lanes = 4 gates x 8 units, HW tanh;
        //      lanes 0-7 publish the CTA's 8 tagged slots in one instruction ----
        if (w == 0) {
            const int q = lane >> 3, u = lane & 7;
            const float val = gate_s[lane] + gsl[t * 32 + lane];
            const float act = (q == 2) ? tanh_hw(val) : sig_hw(val);
            const float iv = __shfl_sync(0xffffffffu, act, u);
            const float fv = __shfl_sync(0xffffffffu, act, u + 8);
            const float gv = __shfl_sync(0xffffffffu, act, u + 16);
            const float ov = __shfl_sync(0xffffffffu, act, u + 24);
            if (lane < 8) {
                const float cc = fv * c_s[u] + iv * gv;
                c_s[u] = cc;
                const float hh = ov * tanh_hw(cc);
                const unsigned long long slot =
                    ((unsigned long long)(unsigned)(t + 1) << 32) |
                    (unsigned long long)__float_as_uint(hh);
                st_rlx64(&g_hslot[(t + 1) & 1][base + u], slot);
                if (t >= SLEN) g_Hbf[(size_t)(t - SLEN) * HD + base + u] = __float2bfloat16(hh);
            }
        }
        // Warps 1..7 roll straight into the next poll. h_s/gate_s reuse is fenced
        // by the two barriers above; slot-buffer reuse (parity) is safe because a
        // CTA reaching step t+2 implies every CTA finished polling step t+1.
    }
}

// ---------------- 5) logits = H @ linW^T + lin_b, tensor cores ----------------
__global__ void __launch_bounds__(128) logits_mma(const float* __restrict__ lin_b,
                                                  float* __restrict__ out) {
    const int tid = threadIdx.x;
    const int w = tid >> 5, lane = tid & 31;
    const int group = lane >> 2, tig = lane & 3;
    const size_t bm = (size_t)blockIdx.x * 128 + w * 32;
    const int bn = blockIdx.y * 64;

    float acc[2][8][4];
    #pragma unroll
    for (int mf = 0; mf < 2; mf++)
        #pragma unroll
        for (int nf = 0; nf < 8; nf++)
            #pragma unroll
            for (int q = 0; q < 4; q++) acc[mf][nf][q] = 0.f;

    for (int k0 = 0; k0 < HD; k0 += 16) {
        unsigned a[2][4], b[8][2];
        #pragma unroll
        for (int mf = 0; mf < 2; mf++) {
            const __nv_bfloat16* ab = g_linw_bf + (bm + mf * 16 + group) * HD + k0 + 2 * tig;
            a[mf][0] = *(const unsigned*)(ab);
            a[mf][1] = *(const unsigned*)(ab + 8 * HD);
            a[mf][2] = *(const unsigned*)(ab + 8);
            a[mf][3] = *(const unsigned*)(ab + 8 * HD + 8);
        }
        #pragma unroll
        for (int nf = 0; nf < 8; nf++) {
            const __nv_bfloat16* bb = g_Hbf + (size_t)(bn + nf * 8 + group) * HD + k0 + 2 * tig;
            b[nf][0] = *(const unsigned*)(bb);
            b[nf][1] = *(const unsigned*)(bb + 8);
        }
        #pragma unroll
        for (int mf = 0; mf < 2; mf++)
            #pragma unroll
            for (int nf = 0; nf < 8; nf++)
                mma_bf16(acc[mf][nf], a[mf][0], a[mf][1], a[mf][2], a[mf][3],
                         b[nf][0], b[nf][1]);
    }
    #pragma unroll
    for (int mf = 0; mf < 2; mf++) {
        const size_t m0 = bm + mf * 16 + group;
        const float bias0 = lin_b[m0];
        const float bias8 = lin_b[m0 + 8];
        #pragma unroll
        for (int nf = 0; nf < 8; nf++) {
            const int n = bn + nf * 8 + 2 * tig;
            out[(size_t)n * VOUT + m0]           = acc[mf][nf][0] + bias0;
            out[(size_t)(n + 1) * VOUT + m0]     = acc[mf][nf][1] + bias0;
            out[(size_t)n * VOUT + m0 + 8]       = acc[mf][nf][2] + bias8;
            out[(size_t)(n + 1) * VOUT + m0 + 8] = acc[mf][nf][3] + bias8;
        }
    }
}

// ---------------- 6) in-place row log_softmax (online) ----------------
__global__ void __launch_bounds__(256) logsoftmax_kernel(float* __restrict__ out) {
    const int t = blockIdx.x;
    float* row = out + (size_t)t * VOUT;
    const int tid = threadIdx.x;
    __shared__ float smx[8], ssm[8];
    __shared__ float sbcast;

    float m = -3.4e38f, s = 0.f;
    for (int i = tid; i < VOUT; i += 256) {
        const float v = row[i];
        const float nm = fmaxf(m, v);
        s = s * __expf(m - nm) + __expf(v - nm);
        m = nm;
    }
    #pragma unroll
    for (int o = 16; o; o >>= 1) {
        const float mo = __shfl_xor_sync(0xffffffffu, m, o);
        const float so = __shfl_xor_sync(0xffffffffu, s, o);
        const float nm = fmaxf(m, mo);
        s = s * __expf(m - nm) + so * __expf(mo - nm);
        m = nm;
    }
    if ((tid & 31) == 0) { smx[tid >> 5] = m; ssm[tid >> 5] = s; }
    __syncthreads();
    if (tid == 0) {
        float M = smx[0], S = ssm[0];
        for (int wq = 1; wq < 8; wq++) {
            const float nm = fmaxf(M, smx[wq]);
            S = S * __expf(M - nm) + ssm[wq] * __expf(smx[wq] - nm);
            M = nm;
        }
        sbcast = M + logf(S);
    }
    __syncthreads();
    const float lse = sbcast;
    for (int i = tid; i < VOUT; i += 256) row[i] -= lse;
}

// ---------------- launch ----------------
extern "C" void kernel_launch(void* const* d_in, const int* in_sizes, int n_in,
                              void* d_out, int out_size) {
    const int*   src     = (const int*)d_in[0];
    const int*   trg     = (const int*)d_in[1];
    const int*   start   = (const int*)d_in[2];
    const float* enc_emb = (const float*)d_in[3];
    const float* enc_Wih = (const float*)d_in[4];
    const float* enc_Whh = (const float*)d_in[5];
    const float* enc_bih = (const float*)d_in[6];
    const float* enc_bhh = (const float*)d_in[7];
    const float* dec_emb = (const float*)d_in[8];
    const float* dec_Wih = (const float*)d_in[9];
    const float* dec_Whh = (const float*)d_in[10];
    const float* dec_bih = (const float*)d_in[11];
    const float* dec_bhh = (const float*)d_in[12];
    const float* lin_W   = (const float*)d_in[13];
    const float* lin_b   = (const float*)d_in[14];
    float* out = (float*)d_out;

    embed_kernel<<<STEPS, 256>>>(src, trg, start, enc_emb, dec_emb);
    convert_kernel<<<2048, 256>>>(enc_Wih, dec_Wih, lin_W);

    dim3 gwx(G4 / 128, SLEN / 64, 2);
    wx_mma<<<gwx, 128>>>(enc_bih, enc_bhh, dec_bih, dec_bhh);

    const int REC_SMEM = (STEPS * 32 + HD + 32 + 8) * 4;   // ~70 KB
    cudaFuncSetAttribute(rec_kernel, cudaFuncAttributeMaxDynamicSharedMemorySize, REC_SMEM);
    rec_kernel<<<NCTA_REC, 256, REC_SMEM>>>(enc_Whh, dec_Whh);

    dim3 gl(VOUT / 128, TLEN / 64);
    logits_mma<<<gl, 128>>>(lin_b, out);

    logsoftmax_kernel<<<TLEN, 256>>>(out);
}

// round 8
// speedup vs baseline: 2.6081x; 1.2342x over previous
#include <cuda_runtime.h>
#include <cuda_bf16.h>

#define HD    1024
#define SLEN  256
#define TLEN  256
#define VOUT  32000
#define G4    4096
#define NCTA_REC 128
#define STEPS 512

// ---------------- device scratch ----------------
__device__ __nv_bfloat16 g_linw_bf[(size_t)VOUT * HD];   // 65.5 MB
__device__ __nv_bfloat16 g_wih_bf[2ul * G4 * HD];        // 16.8 MB
__device__ __nv_bfloat16 g_xbf[(size_t)STEPS * HD];      // 1 MB
__device__ float         g_G[2ul * SLEN * G4];           // 8 MB
__device__ __nv_bfloat16 g_Hbf[(size_t)TLEN * HD];       // 0.5 MB
__device__ float         g_hbuf[2][HD];
__device__ unsigned      g_cnt[STEPS + 1];

// ---------------- helpers ----------------
__device__ __forceinline__ void ffma2(unsigned long long &d,
                                      unsigned long long a, unsigned long long b) {
    asm("fma.rn.f32x2 %0, %1, %2, %0;" : "+l"(d) : "l"(a), "l"(b));
}
__device__ __forceinline__ void unpack2(unsigned long long v, float &lo, float &hi) {
    unsigned l, h;
    asm("mov.b64 {%0, %1}, %2;" : "=r"(l), "=r"(h) : "l"(v));
    lo = __uint_as_float(l); hi = __uint_as_float(h);
}
__device__ __forceinline__ unsigned ld_acq(const unsigned* p) {
    unsigned v;
    asm volatile("ld.acquire.gpu.global.u32 %0, [%1];" : "=r"(v) : "l"(p) : "memory");
    return v;
}
__device__ __forceinline__ void red_rel(unsigned* p) {
    asm volatile("red.release.gpu.global.add.u32 [%0], 1;" :: "l"(p) : "memory");
}
__device__ __forceinline__ float tanh_hw(float x) {
    float y;
    asm("tanh.approx.f32 %0, %1;" : "=f"(y) : "f"(x));
    return y;
}
__device__ __forceinline__ float sig_hw(float x) {
    return fmaf(tanh_hw(0.5f * x), 0.5f, 0.5f);
}
__device__ __forceinline__ void mma_bf16(float c[4],
                                         unsigned a0, unsigned a1, unsigned a2, unsigned a3,
                                         unsigned b0, unsigned b1) {
    asm volatile("mma.sync.aligned.m16n8k16.row.col.f32.bf16.bf16.f32 "
                 "{%0,%1,%2,%3}, {%4,%5,%6,%7}, {%8,%9}, {%0,%1,%2,%3};"
                 : "+f"(c[0]), "+f"(c[1]), "+f"(c[2]), "+f"(c[3])
                 : "r"(a0), "r"(a1), "r"(a2), "r"(a3), "r"(b0), "r"(b1));
}

// ---------------- 1) embedding gather (f32 -> bf16) + counter reset ----------------
__global__ void embed_kernel(const int* __restrict__ src, const int* __restrict__ trg,
                             const int* __restrict__ start,
                             const float* __restrict__ enc_emb,
                             const float* __restrict__ dec_emb) {
    const int t = blockIdx.x;           // 0..511
    const int tid = threadIdx.x;        // 256
    if (t == 0) {                       // re-zero per-step counters every launch/replay
        for (int i = tid; i < STEPS + 1; i += 256) g_cnt[i] = 0;
    }
    const float* emb; int tok;
    if (t < SLEN) { tok = src[t]; emb = enc_emb; }
    else {
        int tt = t - SLEN;
        tok = (tt == 0) ? start[0] : trg[tt - 1];
        emb = dec_emb;
    }
    const float4 v = ((const float4*)(emb + (size_t)tok * HD))[tid];
    __nv_bfloat162 p0 = __floats2bfloat162_rn(v.x, v.y);
    __nv_bfloat162 p1 = __floats2bfloat162_rn(v.z, v.w);
    __nv_bfloat162* d = (__nv_bfloat162*)(g_xbf + (size_t)t * HD);
    d[2 * tid]     = p0;
    d[2 * tid + 1] = p1;
}

// ---------------- 2) f32 -> bf16 weight conversion ----------------
__global__ void convert_kernel(const float* __restrict__ encWih,
                               const float* __restrict__ decWih,
                               const float* __restrict__ linW) {
    size_t i = (size_t)blockIdx.x * blockDim.x + threadIdx.x;
    size_t stride = (size_t)gridDim.x * blockDim.x;
    const size_t NW = (size_t)G4 * HD;
    for (size_t j = i; j < NW; j += stride) {
        g_wih_bf[j]      = __float2bfloat16(encWih[j]);
        g_wih_bf[NW + j] = __float2bfloat16(decWih[j]);
    }
    const size_t NL = (size_t)VOUT * HD;
    for (size_t j = i; j < NL; j += stride) g_linw_bf[j] = __float2bfloat16(linW[j]);
}

// ---------------- 3) G = X @ Wih^T + (bih+bhh), tensor cores ----------------
__global__ void __launch_bounds__(128) wx_mma(const float* __restrict__ eb_ih,
                                              const float* __restrict__ eb_hh,
                                              const float* __restrict__ db_ih,
                                              const float* __restrict__ db_hh) {
    const int net = blockIdx.z;
    const __nv_bfloat16* A = g_wih_bf + (size_t)net * G4 * HD;
    const __nv_bfloat16* B = g_xbf + (size_t)net * SLEN * HD;
    const float* bih = net ? db_ih : eb_ih;
    const float* bhh = net ? db_hh : eb_hh;
    float* Gout = g_G + (size_t)net * SLEN * G4;

    const int tid = threadIdx.x;
    const int w = tid >> 5, lane = tid & 31;
    const int group = lane >> 2, tig = lane & 3;
    const int bm = blockIdx.x * 128 + w * 32;
    const int bn = blockIdx.y * 64;

    float acc[2][8][4];
    #pragma unroll
    for (int mf = 0; mf < 2; mf++)
        #pragma unroll
        for (int nf = 0; nf < 8; nf++)
            #pragma unroll
            for (int q = 0; q < 4; q++) acc[mf][nf][q] = 0.f;

    for (int k0 = 0; k0 < HD; k0 += 16) {
        unsigned a[2][4], b[8][2];
        #pragma unroll
        for (int mf = 0; mf < 2; mf++) {
            const __nv_bfloat16* ab = A + (size_t)(bm + mf * 16 + group) * HD + k0 + 2 * tig;
            a[mf][0] = *(const unsigned*)(ab);
            a[mf][1] = *(const unsigned*)(ab + 8 * HD);
            a[mf][2] = *(const unsigned*)(ab + 8);
            a[mf][3] = *(const unsigned*)(ab + 8 * HD + 8);
        }
        #pragma unroll
        for (int nf = 0; nf < 8; nf++) {
            const __nv_bfloat16* bb = B + (size_t)(bn + nf * 8 + group) * HD + k0 + 2 * tig;
            b[nf][0] = *(const unsigned*)(bb);
            b[nf][1] = *(const unsigned*)(bb + 8);
        }
        #pragma unroll
        for (int mf = 0; mf < 2; mf++)
            #pragma unroll
            for (int nf = 0; nf < 8; nf++)
                mma_bf16(acc[mf][nf], a[mf][0], a[mf][1], a[mf][2], a[mf][3],
                         b[nf][0], b[nf][1]);
    }
    #pragma unroll
    for (int mf = 0; mf < 2; mf++) {
        const int m0 = bm + mf * 16 + group;
        const float bias0 = bih[m0] + bhh[m0];
        const float bias8 = bih[m0 + 8] + bhh[m0 + 8];
        #pragma unroll
        for (int nf = 0; nf < 8; nf++) {
            const int n = bn + nf * 8 + 2 * tig;
            Gout[(size_t)n * G4 + m0]           = acc[mf][nf][0] + bias0;
            Gout[(size_t)(n + 1) * G4 + m0]     = acc[mf][nf][1] + bias0;
            Gout[(size_t)n * G4 + m0 + 8]       = acc[mf][nf][2] + bias8;
            Gout[(size_t)(n + 1) * G4 + m0 + 8] = acc[mf][nf][3] + bias8;
        }
    }
}

// ---------------- 4) persistent LSTM recurrence (R2 sync skeleton + HW-tanh cell) ----------------
__device__ __forceinline__ void load_w(ulonglong2 (&wv)[4][8], const float* __restrict__ W,
                                       int w, int lane, int base) {
    #pragma unroll
    for (int j = 0; j < 4; j++) {
        const int r = w * 4 + j, q = r >> 3, u = r & 7;
        const float* row = W + (size_t)(q * HD + base + u) * HD + lane * 4;
        #pragma unroll
        for (int c = 0; c < 8; c++)
            wv[j][c] = *(const ulonglong2*)(row + c * 128);
    }
}

__global__ void __launch_bounds__(256, 1) rec_kernel(const float* __restrict__ encWhh,
                                                     const float* __restrict__ decWhh) {
    extern __shared__ float sm[];
    float* gsl    = sm;                 // [512][32] precomputed Wx+bias gates (r = q*8+u)
    float* h_s    = gsl + STEPS * 32;   // [1024]
    float* gate_s = h_s + HD;           // [32]

    const int tid = threadIdx.x, cta = blockIdx.x;
    const int w = tid >> 5, lane = tid & 31;
    const int base = cta * 8;

    // preload this CTA's G slice for all 512 steps (64 KB)
    for (int i = tid; i < STEPS * 32; i += 256) {
        const int s = i >> 5, r = i & 31, q = r >> 3, u = r & 7;
        gsl[i] = g_G[(size_t)(s >> 8) * SLEN * G4 + (size_t)(s & 255) * G4 + q * HD + base + u];
    }

    // encoder Whh slice -> registers (f32, 128 regs)
    ulonglong2 wv[4][8];
    load_w(wv, encWhh, w, lane, base);

    float cstate = 0.f;     // live in warp 0, lanes 0..7
    if (tid < 8) {
        g_hbuf[0][base + tid] = 0.f;
        __syncwarp(0xff);
        if (tid == 0) red_rel(&g_cnt[0]);
    }
    __syncthreads();    // gsl ready

    for (int t = 0; t < STEPS; t++) {
        if (t == SLEN) load_w(wv, decWhh, w, lane, base);   // phase switch

        if (tid == 0) { while (ld_acq(&g_cnt[t]) < NCTA_REC) {} }
        __syncthreads();
        ((float4*)h_s)[tid] = ((const float4*)g_hbuf[t & 1])[tid];
        __syncthreads();

        // ---- Whh @ h for this CTA's 32 gate rows (packed f32x2 FMA) ----
        unsigned long long acc2[4] = {0ull, 0ull, 0ull, 0ull};
        #pragma unroll
        for (int c = 0; c < 8; c++) {
            const ulonglong2 hv = *(const ulonglong2*)(h_s + lane * 4 + c * 128);
            #pragma unroll
            for (int j = 0; j < 4; j++) {
                ffma2(acc2[j], wv[j][c].x, hv.x);
                ffma2(acc2[j], wv[j][c].y, hv.y);
            }
        }
        float accf[4];
        #pragma unroll
        for (int j = 0; j < 4; j++) {
            float lo, hi; unpack2(acc2[j], lo, hi);
            accf[j] = lo + hi;
        }
        #pragma unroll
        for (int off = 16; off; off >>= 1) {
            #pragma unroll
            for (int j = 0; j < 4; j++)
                accf[j] += __shfl_xor_sync(0xffffffffu, accf[j], off);
        }
        if (lane < 4) gate_s[w * 4 + lane] = accf[lane];
        __syncthreads();

        // ---- LSTM cell in warp 0: 32 lanes = 4 gates x 8 units, HW tanh ----
        if (w == 0) {
            const int q = lane >> 3, u = lane & 7;
            const float val = gate_s[lane] + gsl[t * 32 + lane];
            const float act = (q == 2) ? tanh_hw(val) : sig_hw(val);
            const float iv = __shfl_sync(0xffffffffu, act, u);
            const float fv = __shfl_sync(0xffffffffu, act, u + 8);
            const float gv = __shfl_sync(0xffffffffu, act, u + 16);
            const float ov = __shfl_sync(0xffffffffu, act, u + 24);
            if (lane < 8) {
                cstate = fv * cstate + iv * gv;
                const float hh = ov * tanh_hw(cstate);
                g_hbuf[(t + 1) & 1][base + lane] = hh;
                if (t >= SLEN) g_Hbf[(size_t)(t - SLEN) * HD + base + lane] = __float2bfloat16(hh);
            }
            __syncwarp();
            if (lane == 0) red_rel(&g_cnt[t + 1]);
        }
        // next iteration's first __syncthreads orders gate_s/h_s reuse
    }
}

// ---------------- 5) logits = H @ linW^T + lin_b, tensor cores ----------------
__global__ void __launch_bounds__(128) logits_mma(const float* __restrict__ lin_b,
                                                  float* __restrict__ out) {
    const int tid = threadIdx.x;
    const int w = tid >> 5, lane = tid & 31;
    const int group = lane >> 2, tig = lane & 3;
    const size_t bm = (size_t)blockIdx.x * 128 + w * 32;
    const int bn = blockIdx.y * 64;

    float acc[2][8][4];
    #pragma unroll
    for (int mf = 0; mf < 2; mf++)
        #pragma unroll
        for (int nf = 0; nf < 8; nf++)
            #pragma unroll
            for (int q = 0; q < 4; q++) acc[mf][nf][q] = 0.f;

    for (int k0 = 0; k0 < HD; k0 += 16) {
        unsigned a[2][4], b[8][2];
        #pragma unroll
        for (int mf = 0; mf < 2; mf++) {
            const __nv_bfloat16* ab = g_linw_bf + (bm + mf * 16 + group) * HD + k0 + 2 * tig;
            a[mf][0] = *(const unsigned*)(ab);
            a[mf][1] = *(const unsigned*)(ab + 8 * HD);
            a[mf][2] = *(const unsigned*)(ab + 8);
            a[mf][3] = *(const unsigned*)(ab + 8 * HD + 8);
        }
        #pragma unroll
        for (int nf = 0; nf < 8; nf++) {
            const __nv_bfloat16* bb = g_Hbf + (size_t)(bn + nf * 8 + group) * HD + k0 + 2 * tig;
            b[nf][0] = *(const unsigned*)(bb);
            b[nf][1] = *(const unsigned*)(bb + 8);
        }
        #pragma unroll
        for (int mf = 0; mf < 2; mf++)
            #pragma unroll
            for (int nf = 0; nf < 8; nf++)
                mma_bf16(acc[mf][nf], a[mf][0], a[mf][1], a[mf][2], a[mf][3],
                         b[nf][0], b[nf][1]);
    }
    #pragma unroll
    for (int mf = 0; mf < 2; mf++) {
        const size_t m0 = bm + mf * 16 + group;
        const float bias0 = lin_b[m0];
        const float bias8 = lin_b[m0 + 8];
        #pragma unroll
        for (int nf = 0; nf < 8; nf++) {
            const int n = bn + nf * 8 + 2 * tig;
            out[(size_t)n * VOUT + m0]           = acc[mf][nf][0] + bias0;
            out[(size_t)(n + 1) * VOUT + m0]     = acc[mf][nf][1] + bias0;
            out[(size_t)n * VOUT + m0 + 8]       = acc[mf][nf][2] + bias8;
            out[(size_t)(n + 1) * VOUT + m0 + 8] = acc[mf][nf][3] + bias8;
        }
    }
}

// ---------------- 6) in-place row log_softmax (online) ----------------
__global__ void __launch_bounds__(256) logsoftmax_kernel(float* __restrict__ out) {
    const int t = blockIdx.x;
    float* row = out + (size_t)t * VOUT;
    const int tid = threadIdx.x;
    __shared__ float smx[8], ssm[8];
    __shared__ float sbcast;

    float m = -3.4e38f, s = 0.f;
    for (int i = tid; i < VOUT; i += 256) {
        const float v = row[i];
        const float nm = fmaxf(m, v);
        s = s * __expf(m - nm) + __expf(v - nm);
        m = nm;
    }
    #pragma unroll
    for (int o = 16; o; o >>= 1) {
        const float mo = __shfl_xor_sync(0xffffffffu, m, o);
        const float so = __shfl_xor_sync(0xffffffffu, s, o);
        const float nm = fmaxf(m, mo);
        s = s * __expf(m - nm) + so * __expf(mo - nm);
        m = nm;
    }
    if ((tid & 31) == 0) { smx[tid >> 5] = m; ssm[tid >> 5] = s; }
    __syncthreads();
    if (tid == 0) {
        float M = smx[0], S = ssm[0];
        for (int wq = 1; wq < 8; wq++) {
            const float nm = fmaxf(M, smx[wq]);
            S = S * __expf(M - nm) + ssm[wq] * __expf(smx[wq] - nm);
            M = nm;
        }
        sbcast = M + logf(S);
    }
    __syncthreads();
    const float lse = sbcast;
    for (int i = tid; i < VOUT; i += 256) row[i] -= lse;
}

// ---------------- launch ----------------
extern "C" void kernel_launch(void* const* d_in, const int* in_sizes, int n_in,
                              void* d_out, int out_size) {
    const int*   src     = (const int*)d_in[0];
    const int*   trg     = (const int*)d_in[1];
    const int*   start   = (const int*)d_in[2];
    const float* enc_emb = (const float*)d_in[3];
    const float* enc_Wih = (const float*)d_in[4];
    const float* enc_Whh = (const float*)d_in[5];
    const float* enc_bih = (const float*)d_in[6];
    const float* enc_bhh = (const float*)d_in[7];
    const float* dec_emb = (const float*)d_in[8];
    const float* dec_Wih = (const float*)d_in[9];
    const float* dec_Whh = (const float*)d_in[10];
    const float* dec_bih = (const float*)d_in[11];
    const float* dec_bhh = (const float*)d_in[12];
    const float* lin_W   = (const float*)d_in[13];
    const float* lin_b   = (const float*)d_in[14];
    float* out = (float*)d_out;

    embed_kernel<<<STEPS, 256>>>(src, trg, start, enc_emb, dec_emb);
    convert_kernel<<<2048, 256>>>(enc_Wih, dec_Wih, lin_W);

    dim3 gwx(G4 / 128, SLEN / 64, 2);
    wx_mma<<<gwx, 128>>>(enc_bih, enc_bhh, dec_bih, dec_bhh);

    const int REC_SMEM = (STEPS * 32 + HD + 32) * 4;   // ~69.8 KB
    cudaFuncSetAttribute(rec_kernel, cudaFuncAttributeMaxDynamicSharedMemorySize, REC_SMEM);
    rec_kernel<<<NCTA_REC, 256, REC_SMEM>>>(enc_Whh, dec_Whh);

    dim3 gl(VOUT / 128, TLEN / 64);
    logits_mma<<<gl, 128>>>(lin_b, out);

    logsoftmax_kernel<<<TLEN, 256>>>(out);
}

// round 9
// speedup vs baseline: 2.6888x; 1.0309x over previous
#include <cuda_runtime.h>
#include <cuda_bf16.h>

#define HD    1024
#define SLEN  256
#define TLEN  256
#define VOUT  32000
#define G4    4096
#define NCTA_REC 128
#define NCTA_TOTAL 148
#define STEPS 512

// ---------------- device scratch ----------------
__device__ __nv_bfloat16 g_linw_bf[(size_t)VOUT * HD];   // 65.5 MB
__device__ __nv_bfloat16 g_wih_bf[2ul * G4 * HD];        // 16.8 MB
__device__ __nv_bfloat16 g_xbf[(size_t)STEPS * HD];      // 1 MB
__device__ float         g_G[2ul * SLEN * G4];           // 8 MB
__device__ __nv_bfloat16 g_Hbf[(size_t)TLEN * HD];       // 0.5 MB
__device__ float         g_hbuf[2][HD];
__device__ unsigned      g_cnt[STEPS + 1];

// ---------------- helpers ----------------
__device__ __forceinline__ void ffma2(unsigned long long &d,
                                      unsigned long long a, unsigned long long b) {
    asm("fma.rn.f32x2 %0, %1, %2, %0;" : "+l"(d) : "l"(a), "l"(b));
}
__device__ __forceinline__ void unpack2(unsigned long long v, float &lo, float &hi) {
    unsigned l, h;
    asm("mov.b64 {%0, %1}, %2;" : "=r"(l), "=r"(h) : "l"(v));
    lo = __uint_as_float(l); hi = __uint_as_float(h);
}
__device__ __forceinline__ unsigned ld_acq(const unsigned* p) {
    unsigned v;
    asm volatile("ld.acquire.gpu.global.u32 %0, [%1];" : "=r"(v) : "l"(p) : "memory");
    return v;
}
__device__ __forceinline__ void red_rel(unsigned* p) {
    asm volatile("red.release.gpu.global.add.u32 [%0], 1;" :: "l"(p) : "memory");
}
__device__ __forceinline__ float tanh_hw(float x) {
    float y;
    asm("tanh.approx.f32 %0, %1;" : "=f"(y) : "f"(x));
    return y;
}
__device__ __forceinline__ float sig_hw(float x) {
    return fmaf(tanh_hw(0.5f * x), 0.5f, 0.5f);
}
__device__ __forceinline__ void mma_bf16(float c[4],
                                         unsigned a0, unsigned a1, unsigned a2, unsigned a3,
                                         unsigned b0, unsigned b1) {
    asm volatile("mma.sync.aligned.m16n8k16.row.col.f32.bf16.bf16.f32 "
                 "{%0,%1,%2,%3}, {%4,%5,%6,%7}, {%8,%9}, {%0,%1,%2,%3};"
                 : "+f"(c[0]), "+f"(c[1]), "+f"(c[2]), "+f"(c[3])
                 : "r"(a0), "r"(a1), "r"(a2), "r"(a3), "r"(b0), "r"(b1));
}

// ---------------- 1) embedding gather (f32 -> bf16) + counter reset ----------------
__global__ void embed_kernel(const int* __restrict__ src, const int* __restrict__ trg,
                             const int* __restrict__ start,
                             const float* __restrict__ enc_emb,
                             const float* __restrict__ dec_emb) {
    const int t = blockIdx.x;           // 0..511
    const int tid = threadIdx.x;        // 256
    if (t == 0) {                       // re-zero per-step counters every launch/replay
        for (int i = tid; i < STEPS + 1; i += 256) g_cnt[i] = 0;
    }
    const float* emb; int tok;
    if (t < SLEN) { tok = src[t]; emb = enc_emb; }
    else {
        int tt = t - SLEN;
        tok = (tt == 0) ? start[0] : trg[tt - 1];
        emb = dec_emb;
    }
    const float4 v = ((const float4*)(emb + (size_t)tok * HD))[tid];
    __nv_bfloat162 p0 = __floats2bfloat162_rn(v.x, v.y);
    __nv_bfloat162 p1 = __floats2bfloat162_rn(v.z, v.w);
    __nv_bfloat162* d = (__nv_bfloat162*)(g_xbf + (size_t)t * HD);
    d[2 * tid]     = p0;
    d[2 * tid + 1] = p1;
}

// ---------------- 2) Wih f32 -> bf16 (linW conversion moved into rec_kernel) ----------------
__global__ void convert_kernel(const float* __restrict__ encWih,
                               const float* __restrict__ decWih) {
    size_t i = (size_t)blockIdx.x * blockDim.x + threadIdx.x;
    size_t stride = (size_t)gridDim.x * blockDim.x;
    const size_t NW4 = (size_t)G4 * HD / 4;
    const float4* se = (const float4*)encWih;
    const float4* sd = (const float4*)decWih;
    __nv_bfloat162* de = (__nv_bfloat162*)g_wih_bf;
    __nv_bfloat162* dd = (__nv_bfloat162*)(g_wih_bf + (size_t)G4 * HD);
    for (size_t j = i; j < NW4; j += stride) {
        float4 ve = se[j];
        de[2 * j]     = __floats2bfloat162_rn(ve.x, ve.y);
        de[2 * j + 1] = __floats2bfloat162_rn(ve.z, ve.w);
        float4 vd = sd[j];
        dd[2 * j]     = __floats2bfloat162_rn(vd.x, vd.y);
        dd[2 * j + 1] = __floats2bfloat162_rn(vd.z, vd.w);
    }
}

// ---------------- 3) G = X @ Wih^T + (bih+bhh), tensor cores ----------------
__global__ void __launch_bounds__(128) wx_mma(const float* __restrict__ eb_ih,
                                              const float* __restrict__ eb_hh,
                                              const float* __restrict__ db_ih,
                                              const float* __restrict__ db_hh) {
    const int net = blockIdx.z;
    const __nv_bfloat16* A = g_wih_bf + (size_t)net * G4 * HD;
    const __nv_bfloat16* B = g_xbf + (size_t)net * SLEN * HD;
    const float* bih = net ? db_ih : eb_ih;
    const float* bhh = net ? db_hh : eb_hh;
    float* Gout = g_G + (size_t)net * SLEN * G4;

    const int tid = threadIdx.x;
    const int w = tid >> 5, lane = tid & 31;
    const int group = lane >> 2, tig = lane & 3;
    const int bm = blockIdx.x * 128 + w * 32;
    const int bn = blockIdx.y * 64;

    float acc[2][8][4];
    #pragma unroll
    for (int mf = 0; mf < 2; mf++)
        #pragma unroll
        for (int nf = 0; nf < 8; nf++)
            #pragma unroll
            for (int q = 0; q < 4; q++) acc[mf][nf][q] = 0.f;

    for (int k0 = 0; k0 < HD; k0 += 16) {
        unsigned a[2][4], b[8][2];
        #pragma unroll
        for (int mf = 0; mf < 2; mf++) {
            const __nv_bfloat16* ab = A + (size_t)(bm + mf * 16 + group) * HD + k0 + 2 * tig;
            a[mf][0] = *(const unsigned*)(ab);
            a[mf][1] = *(const unsigned*)(ab + 8 * HD);
            a[mf][2] = *(const unsigned*)(ab + 8);
            a[mf][3] = *(const unsigned*)(ab + 8 * HD + 8);
        }
        #pragma unroll
        for (int nf = 0; nf < 8; nf++) {
            const __nv_bfloat16* bb = B + (size_t)(bn + nf * 8 + group) * HD + k0 + 2 * tig;
            b[nf][0] = *(const unsigned*)(bb);
            b[nf][1] = *(const unsigned*)(bb + 8);
        }
        #pragma unroll
        for (int mf = 0; mf < 2; mf++)
            #pragma unroll
            for (int nf = 0; nf < 8; nf++)
                mma_bf16(acc[mf][nf], a[mf][0], a[mf][1], a[mf][2], a[mf][3],
                         b[nf][0], b[nf][1]);
    }
    #pragma unroll
    for (int mf = 0; mf < 2; mf++) {
        const int m0 = bm + mf * 16 + group;
        const float bias0 = bih[m0] + bhh[m0];
        const float bias8 = bih[m0 + 8] + bhh[m0 + 8];
        #pragma unroll
        for (int nf = 0; nf < 8; nf++) {
            const int n = bn + nf * 8 + 2 * tig;
            Gout[(size_t)n * G4 + m0]           = acc[mf][nf][0] + bias0;
            Gout[(size_t)(n + 1) * G4 + m0]     = acc[mf][nf][1] + bias0;
            Gout[(size_t)n * G4 + m0 + 8]       = acc[mf][nf][2] + bias8;
            Gout[(size_t)(n + 1) * G4 + m0 + 8] = acc[mf][nf][3] + bias8;
        }
    }
}

// ---------------- 4) persistent LSTM recurrence + hidden linW conversion ----------------
// CTAs 0..127: the R8 recurrence (unchanged). CTAs 128..147: convert lin_W to
// bf16 on otherwise-idle SMs, fully hidden under the recurrence's latency chain.
__device__ __forceinline__ void load_w(ulonglong2 (&wv)[4][8], const float* __restrict__ W,
                                       int w, int lane, int base) {
    #pragma unroll
    for (int j = 0; j < 4; j++) {
        const int r = w * 4 + j, q = r >> 3, u = r & 7;
        const float* row = W + (size_t)(q * HD + base + u) * HD + lane * 4;
        #pragma unroll
        for (int c = 0; c < 8; c++)
            wv[j][c] = *(const ulonglong2*)(row + c * 128);
    }
}

__global__ void __launch_bounds__(256, 1) rec_kernel(const float* __restrict__ encWhh,
                                                     const float* __restrict__ decWhh,
                                                     const float* __restrict__ linW) {
    const int tid = threadIdx.x, cta = blockIdx.x;

    if (cta >= NCTA_REC) {
        // ---- linW f32 -> bf16 on the 20 spare SMs (hidden under recurrence) ----
        const size_t NL4 = (size_t)VOUT * HD / 4;
        size_t i = (size_t)(cta - NCTA_REC) * 256 + tid;
        const size_t stride = (size_t)(NCTA_TOTAL - NCTA_REC) * 256;
        const float4* src = (const float4*)linW;
        __nv_bfloat162* dst = (__nv_bfloat162*)g_linw_bf;
        for (size_t j = i; j < NL4; j += stride) {
            const float4 v = src[j];
            dst[2 * j]     = __floats2bfloat162_rn(v.x, v.y);
            dst[2 * j + 1] = __floats2bfloat162_rn(v.z, v.w);
        }
        return;
    }

    extern __shared__ float sm[];
    float* gsl    = sm;                 // [512][32] precomputed Wx+bias gates (r = q*8+u)
    float* h_s    = gsl + STEPS * 32;   // [1024]
    float* gate_s = h_s + HD;           // [32]

    const int w = tid >> 5, lane = tid & 31;
    const int base = cta * 8;

    // preload this CTA's G slice for all 512 steps (64 KB)
    for (int i = tid; i < STEPS * 32; i += 256) {
        const int s = i >> 5, r = i & 31, q = r >> 3, u = r & 7;
        gsl[i] = g_G[(size_t)(s >> 8) * SLEN * G4 + (size_t)(s & 255) * G4 + q * HD + base + u];
    }

    // encoder Whh slice -> registers (f32, 128 regs)
    ulonglong2 wv[4][8];
    load_w(wv, encWhh, w, lane, base);

    float cstate = 0.f;     // live in warp 0, lanes 0..7
    if (tid < 8) {
        g_hbuf[0][base + tid] = 0.f;
        __syncwarp(0xff);
        if (tid == 0) red_rel(&g_cnt[0]);
    }
    __syncthreads();    // gsl ready

    for (int t = 0; t < STEPS; t++) {
        if (t == SLEN) load_w(wv, decWhh, w, lane, base);   // phase switch

        if (tid == 0) { while (ld_acq(&g_cnt[t]) < NCTA_REC) {} }
        __syncthreads();
        ((float4*)h_s)[tid] = ((const float4*)g_hbuf[t & 1])[tid];
        __syncthreads();

        // ---- Whh @ h for this CTA's 32 gate rows (packed f32x2 FMA) ----
        unsigned long long acc2[4] = {0ull, 0ull, 0ull, 0ull};
        #pragma unroll
        for (int c = 0; c < 8; c++) {
            const ulonglong2 hv = *(const ulonglong2*)(h_s + lane * 4 + c * 128);
            #pragma unroll
            for (int j = 0; j < 4; j++) {
                ffma2(acc2[j], wv[j][c].x, hv.x);
                ffma2(acc2[j], wv[j][c].y, hv.y);
            }
        }
        float accf[4];
        #pragma unroll
        for (int j = 0; j < 4; j++) {
            float lo, hi; unpack2(acc2[j], lo, hi);
            accf[j] = lo + hi;
        }
        #pragma unroll
        for (int off = 16; off; off >>= 1) {
            #pragma unroll
            for (int j = 0; j < 4; j++)
                accf[j] += __shfl_xor_sync(0xffffffffu, accf[j], off);
        }
        if (lane < 4) gate_s[w * 4 + lane] = accf[lane];
        __syncthreads();

        // ---- LSTM cell in warp 0: 32 lanes = 4 gates x 8 units, HW tanh ----
        if (w == 0) {
            const int q = lane >> 3, u = lane & 7;
            const float val = gate_s[lane] + gsl[t * 32 + lane];
            const float act = (q == 2) ? tanh_hw(val) : sig_hw(val);
            const float iv = __shfl_sync(0xffffffffu, act, u);
            const float fv = __shfl_sync(0xffffffffu, act, u + 8);
            const float gv = __shfl_sync(0xffffffffu, act, u + 16);
            const float ov = __shfl_sync(0xffffffffu, act, u + 24);
            if (lane < 8) {
                cstate = fv * cstate + iv * gv;
                const float hh = ov * tanh_hw(cstate);
                g_hbuf[(t + 1) & 1][base + lane] = hh;
                if (t >= SLEN) g_Hbf[(size_t)(t - SLEN) * HD + base + lane] = __float2bfloat16(hh);
            }
            __syncwarp();
            if (lane == 0) red_rel(&g_cnt[t + 1]);
        }
        // next iteration's first __syncthreads orders gate_s/h_s reuse
    }
}

// ---------------- 5) logits = H @ linW^T + lin_b, tensor cores ----------------
__global__ void __launch_bounds__(128) logits_mma(const float* __restrict__ lin_b,
                                                  float* __restrict__ out) {
    const int tid = threadIdx.x;
    const int w = tid >> 5, lane = tid & 31;
    const int group = lane >> 2, tig = lane & 3;
    const size_t bm = (size_t)blockIdx.x * 128 + w * 32;
    const int bn = blockIdx.y * 64;

    float acc[2][8][4];
    #pragma unroll
    for (int mf = 0; mf < 2; mf++)
        #pragma unroll
        for (int nf = 0; nf < 8; nf++)
            #pragma unroll
            for (int q = 0; q < 4; q++) acc[mf][nf][q] = 0.f;

    for (int k0 = 0; k0 < HD; k0 += 16) {
        unsigned a[2][4], b[8][2];
        #pragma unroll
        for (int mf = 0; mf < 2; mf++) {
            const __nv_bfloat16* ab = g_linw_bf + (bm + mf * 16 + group) * HD + k0 + 2 * tig;
            a[mf][0] = *(const unsigned*)(ab);
            a[mf][1] = *(const unsigned*)(ab + 8 * HD);
            a[mf][2] = *(const unsigned*)(ab + 8);
            a[mf][3] = *(const unsigned*)(ab + 8 * HD + 8);
        }
        #pragma unroll
        for (int nf = 0; nf < 8; nf++) {
            const __nv_bfloat16* bb = g_Hbf + (size_t)(bn + nf * 8 + group) * HD + k0 + 2 * tig;
            b[nf][0] = *(const unsigned*)(bb);
            b[nf][1] = *(const unsigned*)(bb + 8);
        }
        #pragma unroll
        for (int mf = 0; mf < 2; mf++)
            #pragma unroll
            for (int nf = 0; nf < 8; nf++)
                mma_bf16(acc[mf][nf], a[mf][0], a[mf][1], a[mf][2], a[mf][3],
                         b[nf][0], b[nf][1]);
    }
    #pragma unroll
    for (int mf = 0; mf < 2; mf++) {
        const size_t m0 = bm + mf * 16 + group;
        const float bias0 = lin_b[m0];
        const float bias8 = lin_b[m0 + 8];
        #pragma unroll
        for (int nf = 0; nf < 8; nf++) {
            const int n = bn + nf * 8 + 2 * tig;
            out[(size_t)n * VOUT + m0]           = acc[mf][nf][0] + bias0;
            out[(size_t)(n + 1) * VOUT + m0]     = acc[mf][nf][1] + bias0;
            out[(size_t)n * VOUT + m0 + 8]       = acc[mf][nf][2] + bias8;
            out[(size_t)(n + 1) * VOUT + m0 + 8] = acc[mf][nf][3] + bias8;
        }
    }
}

// ---------------- 6) in-place row log_softmax (online, float4, 512 thr) ----------------
__global__ void __launch_bounds__(512) logsoftmax_kernel(float* __restrict__ out) {
    const int t = blockIdx.x;
    float* row = out + (size_t)t * VOUT;
    const int tid = threadIdx.x;
    __shared__ float smx[16], ssm[16];
    __shared__ float sbcast;

    float4* r4 = (float4*)row;
    float m = -3.4e38f, s = 0.f;
    for (int i = tid; i < VOUT / 4; i += 512) {
        const float4 v = r4[i];
        const float vm = fmaxf(fmaxf(v.x, v.y), fmaxf(v.z, v.w));
        const float nm = fmaxf(m, vm);
        s = s * __expf(m - nm) + __expf(v.x - nm) + __expf(v.y - nm)
                               + __expf(v.z - nm) + __expf(v.w - nm);
        m = nm;
    }
    #pragma unroll
    for (int o = 16; o; o >>= 1) {
        const float mo = __shfl_xor_sync(0xffffffffu, m, o);
        const float so = __shfl_xor_sync(0xffffffffu, s, o);
        const float nm = fmaxf(m, mo);
        s = s * __expf(m - nm) + so * __expf(mo - nm);
        m = nm;
    }
    if ((tid & 31) == 0) { smx[tid >> 5] = m; ssm[tid >> 5] = s; }
    __syncthreads();
    if (tid == 0) {
        float M = smx[0], S = ssm[0];
        for (int wq = 1; wq < 16; wq++) {
            const float nm = fmaxf(M, smx[wq]);
            S = S * __expf(M - nm) + ssm[wq] * __expf(smx[wq] - nm);
            M = nm;
        }
        sbcast = M + logf(S);
    }
    __syncthreads();
    const float lse = sbcast;
    for (int i = tid; i < VOUT / 4; i += 512) {
        float4 v = r4[i];
        v.x -= lse; v.y -= lse; v.z -= lse; v.w -= lse;
        r4[i] = v;
    }
}

// ---------------- launch ----------------
extern "C" void kernel_launch(void* const* d_in, const int* in_sizes, int n_in,
                              void* d_out, int out_size) {
    const int*   src     = (const int*)d_in[0];
    const int*   trg     = (const int*)d_in[1];
    const int*   start   = (const int*)d_in[2];
    const float* enc_emb = (const float*)d_in[3];
    const float* enc_Wih = (const float*)d_in[4];
    const float* enc_Whh = (const float*)d_in[5];
    const float* enc_bih = (const float*)d_in[6];
    const float* enc_bhh = (const float*)d_in[7];
    const float* dec_emb = (const float*)d_in[8];
    const float* dec_Wih = (const float*)d_in[9];
    const float* dec_Whh = (const float*)d_in[10];
    const float* dec_bih = (const float*)d_in[11];
    const float* dec_bhh = (const float*)d_in[12];
    const float* lin_W   = (const float*)d_in[13];
    const float* lin_b   = (const float*)d_in[14];
    float* out = (float*)d_out;

    embed_kernel<<<STEPS, 256>>>(src, trg, start, enc_emb, dec_emb);
    convert_kernel<<<1024, 256>>>(enc_Wih, dec_Wih);

    dim3 gwx(G4 / 128, SLEN / 64, 2);
    wx_mma<<<gwx, 128>>>(enc_bih, enc_bhh, dec_bih, dec_bhh);

    const int REC_SMEM = (STEPS * 32 + HD + 32) * 4;   // ~69.8 KB
    cudaFuncSetAttribute(rec_kernel, cudaFuncAttributeMaxDynamicSharedMemorySize, REC_SMEM);
    rec_kernel<<<NCTA_TOTAL, 256, REC_SMEM>>>(enc_Whh, dec_Whh, lin_W);

    dim3 gl(VOUT / 128, TLEN / 64);
    logits_mma<<<gl, 128>>>(lin_b, out);

    logsoftmax_kernel<<<TLEN, 512>>>(out);
}

// round 10
// speedup vs baseline: 2.6895x; 1.0002x over previous
#include <cuda_runtime.h>
#include <cuda_bf16.h>

#define HD    1024
#define SLEN  256
#define TLEN  256
#define VOUT  32000
#define G4    4096
#define NCTA_REC 128
#define NCTA_TOTAL 148
#define STEPS 512
#define GSL_STRIDE 33   // bank-conflict padding for gsl rows

// ---------------- device scratch ----------------
__device__ __nv_bfloat16 g_linw_bf[(size_t)VOUT * HD];   // 65.5 MB
__device__ __nv_bfloat16 g_wih_bf[2ul * G4 * HD];        // 16.8 MB
__device__ __nv_bfloat16 g_xbf[(size_t)STEPS * HD];      // 1 MB
__device__ float         g_G[2ul * G4 * SLEN];           // 8 MB, [net][gate_row][token]
__device__ __nv_bfloat16 g_Hbf[(size_t)TLEN * HD];       // 0.5 MB
__device__ float         g_hbuf[2][HD];
__device__ unsigned      g_cnt[STEPS + 1];

// ---------------- helpers ----------------
__device__ __forceinline__ void ffma2(unsigned long long &d,
                                      unsigned long long a, unsigned long long b) {
    asm("fma.rn.f32x2 %0, %1, %2, %0;" : "+l"(d) : "l"(a), "l"(b));
}
__device__ __forceinline__ void unpack2(unsigned long long v, float &lo, float &hi) {
    unsigned l, h;
    asm("mov.b64 {%0, %1}, %2;" : "=r"(l), "=r"(h) : "l"(v));
    lo = __uint_as_float(l); hi = __uint_as_float(h);
}
__device__ __forceinline__ unsigned ld_acq(const unsigned* p) {
    unsigned v;
    asm volatile("ld.acquire.gpu.global.u32 %0, [%1];" : "=r"(v) : "l"(p) : "memory");
    return v;
}
__device__ __forceinline__ void red_rel(unsigned* p) {
    asm volatile("red.release.gpu.global.add.u32 [%0], 1;" :: "l"(p) : "memory");
}
__device__ __forceinline__ float tanh_hw(float x) {
    float y;
    asm("tanh.approx.f32 %0, %1;" : "=f"(y) : "f"(x));
    return y;
}
__device__ __forceinline__ float sig_hw(float x) {
    return fmaf(tanh_hw(0.5f * x), 0.5f, 0.5f);
}
__device__ __forceinline__ void mma_bf16(float c[4],
                                         unsigned a0, unsigned a1, unsigned a2, unsigned a3,
                                         unsigned b0, unsigned b1) {
    asm volatile("mma.sync.aligned.m16n8k16.row.col.f32.bf16.bf16.f32 "
                 "{%0,%1,%2,%3}, {%4,%5,%6,%7}, {%8,%9}, {%0,%1,%2,%3};"
                 : "+f"(c[0]), "+f"(c[1]), "+f"(c[2]), "+f"(c[3])
                 : "r"(a0), "r"(a1), "r"(a2), "r"(a3), "r"(b0), "r"(b1));
}

// ---------------- 1) prep: embedding gather + Wih conversion + counter reset ----------------
__global__ void prep_kernel(const int* __restrict__ src, const int* __restrict__ trg,
                            const int* __restrict__ start,
                            const float* __restrict__ enc_emb,
                            const float* __restrict__ dec_emb,
                            const float* __restrict__ encWih,
                            const float* __restrict__ decWih) {
    const int b = blockIdx.x;           // 0..639
    const int tid = threadIdx.x;        // 256
    if (b < STEPS) {
        // ---- embedding gather (f32 -> bf16) ----
        const int t = b;
        if (t == 0) {                   // re-zero per-step counters every launch/replay
            for (int i = tid; i < STEPS + 1; i += 256) g_cnt[i] = 0;
        }
        const float* emb; int tok;
        if (t < SLEN) { tok = src[t]; emb = enc_emb; }
        else {
            int tt = t - SLEN;
            tok = (tt == 0) ? start[0] : trg[tt - 1];
            emb = dec_emb;
        }
        const float4 v = ((const float4*)(emb + (size_t)tok * HD))[tid];
        __nv_bfloat162* d = (__nv_bfloat162*)(g_xbf + (size_t)t * HD);
        d[2 * tid]     = __floats2bfloat162_rn(v.x, v.y);
        d[2 * tid + 1] = __floats2bfloat162_rn(v.z, v.w);
    } else {
        // ---- Wih f32 -> bf16 (both nets), float4-vectorized ----
        const size_t NW4 = (size_t)G4 * HD / 4;
        size_t i = (size_t)(b - STEPS) * 256 + tid;
        const size_t stride = 128ul * 256;
        const float4* se = (const float4*)encWih;
        const float4* sd = (const float4*)decWih;
        __nv_bfloat162* de = (__nv_bfloat162*)g_wih_bf;
        __nv_bfloat162* dd = (__nv_bfloat162*)(g_wih_bf + (size_t)G4 * HD);
        for (size_t j = i; j < NW4; j += stride) {
            const float4 ve = se[j];
            de[2 * j]     = __floats2bfloat162_rn(ve.x, ve.y);
            de[2 * j + 1] = __floats2bfloat162_rn(ve.z, ve.w);
            const float4 vd = sd[j];
            dd[2 * j]     = __floats2bfloat162_rn(vd.x, vd.y);
            dd[2 * j + 1] = __floats2bfloat162_rn(vd.z, vd.w);
        }
    }
}

// ---------------- 3) G^T = Wih @ X^T + (bih+bhh), tensor cores ----------------
// Output layout: g_G[net][m][n]  (m = gate row 0..4095, n = token 0..255)
__global__ void __launch_bounds__(128) wx_mma(const float* __restrict__ eb_ih,
                                              const float* __restrict__ eb_hh,
                                              const float* __restrict__ db_ih,
                                              const float* __restrict__ db_hh) {
    const int net = blockIdx.z;
    const __nv_bfloat16* A = g_wih_bf + (size_t)net * G4 * HD;
    const __nv_bfloat16* B = g_xbf + (size_t)net * SLEN * HD;
    const float* bih = net ? db_ih : eb_ih;
    const float* bhh = net ? db_hh : eb_hh;
    float* Gout = g_G + (size_t)net * G4 * SLEN;

    const int tid = threadIdx.x;
    const int w = tid >> 5, lane = tid & 31;
    const int group = lane >> 2, tig = lane & 3;
    const int bm = blockIdx.x * 128 + w * 32;
    const int bn = blockIdx.y * 64;

    float acc[2][8][4];
    #pragma unroll
    for (int mf = 0; mf < 2; mf++)
        #pragma unroll
        for (int nf = 0; nf < 8; nf++)
            #pragma unroll
            for (int q = 0; q < 4; q++) acc[mf][nf][q] = 0.f;

    for (int k0 = 0; k0 < HD; k0 += 16) {
        unsigned a[2][4], b[8][2];
        #pragma unroll
        for (int mf = 0; mf < 2; mf++) {
            const __nv_bfloat16* ab = A + (size_t)(bm + mf * 16 + group) * HD + k0 + 2 * tig;
            a[mf][0] = *(const unsigned*)(ab);
            a[mf][1] = *(const unsigned*)(ab + 8 * HD);
            a[mf][2] = *(const unsigned*)(ab + 8);
            a[mf][3] = *(const unsigned*)(ab + 8 * HD + 8);
        }
        #pragma unroll
        for (int nf = 0; nf < 8; nf++) {
            const __nv_bfloat16* bb = B + (size_t)(bn + nf * 8 + group) * HD + k0 + 2 * tig;
            b[nf][0] = *(const unsigned*)(bb);
            b[nf][1] = *(const unsigned*)(bb + 8);
        }
        #pragma unroll
        for (int mf = 0; mf < 2; mf++)
            #pragma unroll
            for (int nf = 0; nf < 8; nf++)
                mma_bf16(acc[mf][nf], a[mf][0], a[mf][1], a[mf][2], a[mf][3],
                         b[nf][0], b[nf][1]);
    }
    #pragma unroll
    for (int mf = 0; mf < 2; mf++) {
        const int m0 = bm + mf * 16 + group;
        const float bias0 = bih[m0] + bhh[m0];
        const float bias8 = bih[m0 + 8] + bhh[m0 + 8];
        #pragma unroll
        for (int nf = 0; nf < 8; nf++) {
            const int n = bn + nf * 8 + 2 * tig;
            float2 s0; s0.x = acc[mf][nf][0] + bias0; s0.y = acc[mf][nf][1] + bias0;
            float2 s8; s8.x = acc[mf][nf][2] + bias8; s8.y = acc[mf][nf][3] + bias8;
            *(float2*)&Gout[(size_t)m0 * SLEN + n]       = s0;   // coalesced runs
            *(float2*)&Gout[(size_t)(m0 + 8) * SLEN + n] = s8;
        }
    }
}

// ---------------- 4) persistent LSTM recurrence + hidden linW conversion ----------------
__device__ __forceinline__ void load_w(ulonglong2 (&wv)[4][8], const float* __restrict__ W,
                                       int w, int lane, int base) {
    #pragma unroll
    for (int j = 0; j < 4; j++) {
        const int r = w * 4 + j, q = r >> 3, u = r & 7;
        const float* row = W + (size_t)(q * HD + base + u) * HD + lane * 4;
        #pragma unroll
        for (int c = 0; c < 8; c++)
            wv[j][c] = *(const ulonglong2*)(row + c * 128);
    }
}

__global__ void __launch_bounds__(256, 1) rec_kernel(const float* __restrict__ encWhh,
                                                     const float* __restrict__ decWhh,
                                                     const float* __restrict__ linW) {
    const int tid = threadIdx.x, cta = blockIdx.x;

    if (cta >= NCTA_REC) {
        // ---- linW f32 -> bf16 on the 20 spare SMs (hidden under recurrence) ----
        const size_t NL4 = (size_t)VOUT * HD / 4;
        size_t i = (size_t)(cta - NCTA_REC) * 256 + tid;
        const size_t stride = (size_t)(NCTA_TOTAL - NCTA_REC) * 256;
        const float4* src = (const float4*)linW;
        __nv_bfloat162* dst = (__nv_bfloat162*)g_linw_bf;
        for (size_t j = i; j < NL4; j += stride) {
            const float4 v = src[j];
            dst[2 * j]     = __floats2bfloat162_rn(v.x, v.y);
            dst[2 * j + 1] = __floats2bfloat162_rn(v.z, v.w);
        }
        return;
    }

    extern __shared__ float sm[];
    float* gsl    = sm;                        // [512][GSL_STRIDE] Wx+bias gates
    float* h_s    = gsl + STEPS * GSL_STRIDE;  // [1024]
    float* gate_s = h_s + HD;                  // [32]

    const int w = tid >> 5, lane = tid & 31;
    const int base = cta * 8;

    // preload this CTA's G slice for all 512 steps (coalesced rows of G^T)
    for (int i = tid; i < STEPS * 32; i += 256) {
        const int r = i >> 9, s = i & 511;            // r: gate row 0..31, s: step
        const int net = s >> 8, sl = s & 255;
        const int q = r >> 3, u = r & 7;
        gsl[s * GSL_STRIDE + r] =
            g_G[(size_t)net * G4 * SLEN + (size_t)(q * HD + base + u) * SLEN + sl];
    }

    // encoder Whh slice -> registers (f32, 128 regs)
    ulonglong2 wv[4][8];
    load_w(wv, encWhh, w, lane, base);

    float cstate = 0.f;     // live in warp 0, lanes 0..7
    if (tid < 8) {
        g_hbuf[0][base + tid] = 0.f;
        __syncwarp(0xff);
        if (tid == 0) red_rel(&g_cnt[0]);
    }
    __syncthreads();    // gsl ready

    for (int t = 0; t < STEPS; t++) {
        if (t == SLEN) load_w(wv, decWhh, w, lane, base);   // phase switch

        if (tid == 0) { while (ld_acq(&g_cnt[t]) < NCTA_REC) {} }
        __syncthreads();
        ((float4*)h_s)[tid] = ((const float4*)g_hbuf[t & 1])[tid];
        __syncthreads();

        // ---- Whh @ h for this CTA's 32 gate rows (packed f32x2 FMA) ----
        unsigned long long acc2[4] = {0ull, 0ull, 0ull, 0ull};
        #pragma unroll
        for (int c = 0; c < 8; c++) {
            const ulonglong2 hv = *(const ulonglong2*)(h_s + lane * 4 + c * 128);
            #pragma unroll
            for (int j = 0; j < 4; j++) {
                ffma2(acc2[j], wv[j][c].x, hv.x);
                ffma2(acc2[j], wv[j][c].y, hv.y);
            }
        }
        float accf[4];
        #pragma unroll
        for (int j = 0; j < 4; j++) {
            float lo, hi; unpack2(acc2[j], lo, hi);
            accf[j] = lo + hi;
        }
        #pragma unroll
        for (int off = 16; off; off >>= 1) {
            #pragma unroll
            for (int j = 0; j < 4; j++)
                accf[j] += __shfl_xor_sync(0xffffffffu, accf[j], off);
        }
        if (lane < 4) gate_s[w * 4 + lane] = accf[lane];
        __syncthreads();

        // ---- LSTM cell in warp 0: 32 lanes = 4 gates x 8 units, HW tanh ----
        if (w == 0) {
            const int q = lane >> 3, u = lane & 7;
            const float val = gate_s[lane] + gsl[t * GSL_STRIDE + lane];
            const float act = (q == 2) ? tanh_hw(val) : sig_hw(val);
            const float iv = __shfl_sync(0xffffffffu, act, u);
            const float fv = __shfl_sync(0xffffffffu, act, u + 8);
            const float gv = __shfl_sync(0xffffffffu, act, u + 16);
            const float ov = __shfl_sync(0xffffffffu, act, u + 24);
            if (lane < 8) {
                cstate = fv * cstate + iv * gv;
                const float hh = ov * tanh_hw(cstate);
                g_hbuf[(t + 1) & 1][base + lane] = hh;
                if (t >= SLEN) g_Hbf[(size_t)(t - SLEN) * HD + base + lane] = __float2bfloat16(hh);
            }
            __syncwarp();
            if (lane == 0) red_rel(&g_cnt[t + 1]);
        }
        // next iteration's first __syncthreads orders gate_s/h_s reuse
    }
}

// ---------------- 5) logits = H @ linW^T + lin_b, tensor cores (256 thr) ----------------
__global__ void __launch_bounds__(256) logits_mma(const float* __restrict__ lin_b,
                                                  float* __restrict__ out) {
    const int tid = threadIdx.x;
    const int w = tid >> 5, lane = tid & 31;
    const int group = lane >> 2, tig = lane & 3;
    const size_t bm = (size_t)blockIdx.x * 256 + w * 32;
    const int bn = blockIdx.y * 64;

    float acc[2][8][4];
    #pragma unroll
    for (int mf = 0; mf < 2; mf++)
        #pragma unroll
        for (int nf = 0; nf < 8; nf++)
            #pragma unroll
            for (int q = 0; q < 4; q++) acc[mf][nf][q] = 0.f;

    for (int k0 = 0; k0 < HD; k0 += 16) {
        unsigned a[2][4], b[8][2];
        #pragma unroll
        for (int mf = 0; mf < 2; mf++) {
            const __nv_bfloat16* ab = g_linw_bf + (bm + mf * 16 + group) * HD + k0 + 2 * tig;
            a[mf][0] = *(const unsigned*)(ab);
            a[mf][1] = *(const unsigned*)(ab + 8 * HD);
            a[mf][2] = *(const unsigned*)(ab + 8);
            a[mf][3] = *(const unsigned*)(ab + 8 * HD + 8);
        }
        #pragma unroll
        for (int nf = 0; nf < 8; nf++) {
            const __nv_bfloat16* bb = g_Hbf + (size_t)(bn + nf * 8 + group) * HD + k0 + 2 * tig;
            b[nf][0] = *(const unsigned*)(bb);
            b[nf][1] = *(const unsigned*)(bb + 8);
        }
        #pragma unroll
        for (int mf = 0; mf < 2; mf++)
            #pragma unroll
            for (int nf = 0; nf < 8; nf++)
                mma_bf16(acc[mf][nf], a[mf][0], a[mf][1], a[mf][2], a[mf][3],
                         b[nf][0], b[nf][1]);
    }
    #pragma unroll
    for (int mf = 0; mf < 2; mf++) {
        const size_t m0 = bm + mf * 16 + group;
        const float bias0 = lin_b[m0];
        const float bias8 = lin_b[m0 + 8];
        #pragma unroll
        for (int nf = 0; nf < 8; nf++) {
            const int n = bn + nf * 8 + 2 * tig;
            out[(size_t)n * VOUT + m0]           = acc[mf][nf][0] + bias0;
            out[(size_t)(n + 1) * VOUT + m0]     = acc[mf][nf][1] + bias0;
            out[(size_t)n * VOUT + m0 + 8]       = acc[mf][nf][2] + bias8;
            out[(size_t)(n + 1) * VOUT + m0 + 8] = acc[mf][nf][3] + bias8;
        }
    }
}

// ---------------- 6) in-place row log_softmax (online, float4, 512 thr) ----------------
__global__ void __launch_bounds__(512) logsoftmax_kernel(float* __restrict__ out) {
    const int t = blockIdx.x;
    float* row = out + (size_t)t * VOUT;
    const int tid = threadIdx.x;
    __shared__ float smx[16], ssm[16];
    __shared__ float sbcast;

    float4* r4 = (float4*)row;
    float m = -3.4e38f, s = 0.f;
    for (int i = tid; i < VOUT / 4; i += 512) {
        const float4 v = r4[i];
        const float vm = fmaxf(fmaxf(v.x, v.y), fmaxf(v.z, v.w));
        const float nm = fmaxf(m, vm);
        s = s * __expf(m - nm) + __expf(v.x - nm) + __expf(v.y - nm)
                               + __expf(v.z - nm) + __expf(v.w - nm);
        m = nm;
    }
    #pragma unroll
    for (int o = 16; o; o >>= 1) {
        const float mo = __shfl_xor_sync(0xffffffffu, m, o);
        const float so = __shfl_xor_sync(0xffffffffu, s, o);
        const float nm = fmaxf(m, mo);
        s = s * __expf(m - nm) + so * __expf(mo - nm);
        m = nm;
    }
    if ((tid & 31) == 0) { smx[tid >> 5] = m; ssm[tid >> 5] = s; }
    __syncthreads();
    if (tid == 0) {
        float M = smx[0], S = ssm[0];
        for (int wq = 1; wq < 16; wq++) {
            const float nm = fmaxf(M, smx[wq]);
            S = S * __expf(M - nm) + ssm[wq] * __expf(smx[wq] - nm);
            M = nm;
        }
        sbcast = M + logf(S);
    }
    __syncthreads();
    const float lse = sbcast;
    for (int i = tid; i < VOUT / 4; i += 512) {
        float4 v = r4[i];
        v.x -= lse; v.y -= lse; v.z -= lse; v.w -= lse;
        r4[i] = v;
    }
}

// ---------------- launch ----------------
extern "C" void kernel_launch(void* const* d_in, const int* in_sizes, int n_in,
                              void* d_out, int out_size) {
    const int*   src     = (const int*)d_in[0];
    const int*   trg     = (const int*)d_in[1];
    const int*   start   = (const int*)d_in[2];
    const float* enc_emb = (const float*)d_in[3];
    const float* enc_Wih = (const float*)d_in[4];
    const float* enc_Whh = (const float*)d_in[5];
    const float* enc_bih = (const float*)d_in[6];
    const float* enc_bhh = (const float*)d_in[7];
    const float* dec_emb = (const float*)d_in[8];
    const float* dec_Wih = (const float*)d_in[9];
    const float* dec_Whh = (const float*)d_in[10];
    const float* dec_bih = (const float*)d_in[11];
    const float* dec_bhh = (const float*)d_in[12];
    const float* lin_W   = (const float*)d_in[13];
    const float* lin_b   = (const float*)d_in[14];
    float* out = (float*)d_out;

    prep_kernel<<<STEPS + 128, 256>>>(src, trg, start, enc_emb, dec_emb,
                                      enc_Wih, dec_Wih);

    dim3 gwx(G4 / 128, SLEN / 64, 2);
    wx_mma<<<gwx, 128>>>(enc_bih, enc_bhh, dec_bih, dec_bhh);

    const int REC_SMEM = (STEPS * GSL_STRIDE + HD + 32) * 4;   // ~71.8 KB
    cudaFuncSetAttribute(rec_kernel, cudaFuncAttributeMaxDynamicSharedMemorySize, REC_SMEM);
    rec_kernel<<<NCTA_TOTAL, 256, REC_SMEM>>>(enc_Whh, dec_Whh, lin_W);

    dim3 gl(VOUT / 256, TLEN / 64);
    logits_mma<<<gl, 256>>>(lin_b, out);

    logsoftmax_kernel<<<TLEN, 512>>>(out);
}

// round 11
// speedup vs baseline: 2.9919x; 1.1125x over previous
#include <cuda_runtime.h>
#include <cuda_bf16.h>

#define HD    1024
#define SLEN  256
#define TLEN  256
#define VOUT  32000
#define G4    4096
#define NCTA_REC 128
#define NCTA_TOTAL 148
#define STEPS 512
#define GSL_STRIDE 33   // bank-conflict padding for gsl rows
#define LPAD 72         // smem row padding (bf16) for conflict-free ldmatrix

// ---------------- device scratch ----------------
__device__ __nv_bfloat16 g_linw_bf[(size_t)VOUT * HD];   // 65.5 MB
__device__ __nv_bfloat16 g_wih_bf[2ul * G4 * HD];        // 16.8 MB
__device__ __nv_bfloat16 g_xbf[(size_t)STEPS * HD];      // 1 MB
__device__ float         g_G[2ul * G4 * SLEN];           // 8 MB, [net][gate_row][token]
__device__ __nv_bfloat16 g_Hbf[(size_t)TLEN * HD];       // 0.5 MB
__device__ float         g_hbuf[2][HD];
__device__ unsigned      g_cnt[STEPS + 1];

// ---------------- helpers ----------------
__device__ __forceinline__ void ffma2(unsigned long long &d,
                                      unsigned long long a, unsigned long long b) {
    asm("fma.rn.f32x2 %0, %1, %2, %0;" : "+l"(d) : "l"(a), "l"(b));
}
__device__ __forceinline__ void unpack2(unsigned long long v, float &lo, float &hi) {
    unsigned l, h;
    asm("mov.b64 {%0, %1}, %2;" : "=r"(l), "=r"(h) : "l"(v));
    lo = __uint_as_float(l); hi = __uint_as_float(h);
}
__device__ __forceinline__ unsigned ld_acq(const unsigned* p) {
    unsigned v;
    asm volatile("ld.acquire.gpu.global.u32 %0, [%1];" : "=r"(v) : "l"(p) : "memory");
    return v;
}
__device__ __forceinline__ void red_rel(unsigned* p) {
    asm volatile("red.release.gpu.global.add.u32 [%0], 1;" :: "l"(p) : "memory");
}
__device__ __forceinline__ float tanh_hw(float x) {
    float y;
    asm("tanh.approx.f32 %0, %1;" : "=f"(y) : "f"(x));
    return y;
}
__device__ __forceinline__ float sig_hw(float x) {
    return fmaf(tanh_hw(0.5f * x), 0.5f, 0.5f);
}
__device__ __forceinline__ void mma_bf16(float c[4],
                                         unsigned a0, unsigned a1, unsigned a2, unsigned a3,
                                         unsigned b0, unsigned b1) {
    asm volatile("mma.sync.aligned.m16n8k16.row.col.f32.bf16.bf16.f32 "
                 "{%0,%1,%2,%3}, {%4,%5,%6,%7}, {%8,%9}, {%0,%1,%2,%3};"
                 : "+f"(c[0]), "+f"(c[1]), "+f"(c[2]), "+f"(c[3])
                 : "r"(a0), "r"(a1), "r"(a2), "r"(a3), "r"(b0), "r"(b1));
}
__device__ __forceinline__ unsigned smem_u32(const void* p) {
    return (unsigned)__cvta_generic_to_shared(p);
}
__device__ __forceinline__ void ldsm_x4(unsigned &r0, unsigned &r1,
                                        unsigned &r2, unsigned &r3, unsigned addr) {
    asm volatile("ldmatrix.sync.aligned.m8n8.x4.shared.b16 {%0,%1,%2,%3}, [%4];"
                 : "=r"(r0), "=r"(r1), "=r"(r2), "=r"(r3) : "r"(addr));
}

// ---------------- 1) prep: embedding gather + Wih conversion + counter reset ----------------
__global__ void prep_kernel(const int* __restrict__ src, const int* __restrict__ trg,
                            const int* __restrict__ start,
                            const float* __restrict__ enc_emb,
                            const float* __restrict__ dec_emb,
                            const float* __restrict__ encWih,
                            const float* __restrict__ decWih) {
    const int b = blockIdx.x;           // 0..639
    const int tid = threadIdx.x;        // 256
    if (b < STEPS) {
        const int t = b;
        if (t == 0) {
            for (int i = tid; i < STEPS + 1; i += 256) g_cnt[i] = 0;
        }
        const float* emb; int tok;
        if (t < SLEN) { tok = src[t]; emb = enc_emb; }
        else {
            int tt = t - SLEN;
            tok = (tt == 0) ? start[0] : trg[tt - 1];
            emb = dec_emb;
        }
        const float4 v = ((const float4*)(emb + (size_t)tok * HD))[tid];
        __nv_bfloat162* d = (__nv_bfloat162*)(g_xbf + (size_t)t * HD);
        d[2 * tid]     = __floats2bfloat162_rn(v.x, v.y);
        d[2 * tid + 1] = __floats2bfloat162_rn(v.z, v.w);
    } else {
        const size_t NW4 = (size_t)G4 * HD / 4;
        size_t i = (size_t)(b - STEPS) * 256 + tid;
        const size_t stride = 128ul * 256;
        const float4* se = (const float4*)encWih;
        const float4* sd = (const float4*)decWih;
        __nv_bfloat162* de = (__nv_bfloat162*)g_wih_bf;
        __nv_bfloat162* dd = (__nv_bfloat162*)(g_wih_bf + (size_t)G4 * HD);
        for (size_t j = i; j < NW4; j += stride) {
            const float4 ve = se[j];
            de[2 * j]     = __floats2bfloat162_rn(ve.x, ve.y);
            de[2 * j + 1] = __floats2bfloat162_rn(ve.z, ve.w);
            const float4 vd = sd[j];
            dd[2 * j]     = __floats2bfloat162_rn(vd.x, vd.y);
            dd[2 * j + 1] = __floats2bfloat162_rn(vd.z, vd.w);
        }
    }
}

// ---------------- 3) G^T = Wih @ X^T + (bih+bhh), tensor cores ----------------
__global__ void __launch_bounds__(128) wx_mma(const float* __restrict__ eb_ih,
                                              const float* __restrict__ eb_hh,
                                              const float* __restrict__ db_ih,
                                              const float* __restrict__ db_hh) {
    const int net = blockIdx.z;
    const __nv_bfloat16* A = g_wih_bf + (size_t)net * G4 * HD;
    const __nv_bfloat16* B = g_xbf + (size_t)net * SLEN * HD;
    const float* bih = net ? db_ih : eb_ih;
    const float* bhh = net ? db_hh : eb_hh;
    float* Gout = g_G + (size_t)net * G4 * SLEN;

    const int tid = threadIdx.x;
    const int w = tid >> 5, lane = tid & 31;
    const int group = lane >> 2, tig = lane & 3;
    const int bm = blockIdx.x * 128 + w * 32;
    const int bn = blockIdx.y * 64;

    float acc[2][8][4];
    #pragma unroll
    for (int mf = 0; mf < 2; mf++)
        #pragma unroll
        for (int nf = 0; nf < 8; nf++)
            #pragma unroll
            for (int q = 0; q < 4; q++) acc[mf][nf][q] = 0.f;

    for (int k0 = 0; k0 < HD; k0 += 16) {
        unsigned a[2][4], b[8][2];
        #pragma unroll
        for (int mf = 0; mf < 2; mf++) {
            const __nv_bfloat16* ab = A + (size_t)(bm + mf * 16 + group) * HD + k0 + 2 * tig;
            a[mf][0] = *(const unsigned*)(ab);
            a[mf][1] = *(const unsigned*)(ab + 8 * HD);
            a[mf][2] = *(const unsigned*)(ab + 8);
            a[mf][3] = *(const unsigned*)(ab + 8 * HD + 8);
        }
        #pragma unroll
        for (int nf = 0; nf < 8; nf++) {
            const __nv_bfloat16* bb = B + (size_t)(bn + nf * 8 + group) * HD + k0 + 2 * tig;
            b[nf][0] = *(const unsigned*)(bb);
            b[nf][1] = *(const unsigned*)(bb + 8);
        }
        #pragma unroll
        for (int mf = 0; mf < 2; mf++)
            #pragma unroll
            for (int nf = 0; nf < 8; nf++)
                mma_bf16(acc[mf][nf], a[mf][0], a[mf][1], a[mf][2], a[mf][3],
                         b[nf][0], b[nf][1]);
    }
    #pragma unroll
    for (int mf = 0; mf < 2; mf++) {
        const int m0 = bm + mf * 16 + group;
        const float bias0 = bih[m0] + bhh[m0];
        const float bias8 = bih[m0 + 8] + bhh[m0 + 8];
        #pragma unroll
        for (int nf = 0; nf < 8; nf++) {
            const int n = bn + nf * 8 + 2 * tig;
            float2 s0; s0.x = acc[mf][nf][0] + bias0; s0.y = acc[mf][nf][1] + bias0;
            float2 s8; s8.x = acc[mf][nf][2] + bias8; s8.y = acc[mf][nf][3] + bias8;
            *(float2*)&Gout[(size_t)m0 * SLEN + n]       = s0;
            *(float2*)&Gout[(size_t)(m0 + 8) * SLEN + n] = s8;
        }
    }
}

// ---------------- 4) persistent LSTM recurrence + hidden linW conversion ----------------
__device__ __forceinline__ void load_w(ulonglong2 (&wv)[4][8], const float* __restrict__ W,
                                       int w, int lane, int base) {
    #pragma unroll
    for (int j = 0; j < 4; j++) {
        const int r = w * 4 + j, q = r >> 3, u = r & 7;
        const float* row = W + (size_t)(q * HD + base + u) * HD + lane * 4;
        #pragma unroll
        for (int c = 0; c < 8; c++)
            wv[j][c] = *(const ulonglong2*)(row + c * 128);
    }
}

__global__ void __launch_bounds__(256, 1) rec_kernel(const float* __restrict__ encWhh,
                                                     const float* __restrict__ decWhh,
                                                     const float* __restrict__ linW) {
    const int tid = threadIdx.x, cta = blockIdx.x;

    if (cta >= NCTA_REC) {
        const size_t NL4 = (size_t)VOUT * HD / 4;
        size_t i = (size_t)(cta - NCTA_REC) * 256 + tid;
        const size_t stride = (size_t)(NCTA_TOTAL - NCTA_REC) * 256;
        const float4* src = (const float4*)linW;
        __nv_bfloat162* dst = (__nv_bfloat162*)g_linw_bf;
        for (size_t j = i; j < NL4; j += stride) {
            const float4 v = src[j];
            dst[2 * j]     = __floats2bfloat162_rn(v.x, v.y);
            dst[2 * j + 1] = __floats2bfloat162_rn(v.z, v.w);
        }
        return;
    }

    extern __shared__ float sm[];
    float* gsl    = sm;                        // [512][GSL_STRIDE] Wx+bias gates
    float* h_s    = gsl + STEPS * GSL_STRIDE;  // [1024]
    float* gate_s = h_s + HD;                  // [32]

    const int w = tid >> 5, lane = tid & 31;
    const int base = cta * 8;

    for (int i = tid; i < STEPS * 32; i += 256) {
        const int r = i >> 9, s = i & 511;
        const int net = s >> 8, sl = s & 255;
        const int q = r >> 3, u = r & 7;
        gsl[s * GSL_STRIDE + r] =
            g_G[(size_t)net * G4 * SLEN + (size_t)(q * HD + base + u) * SLEN + sl];
    }

    ulonglong2 wv[4][8];
    load_w(wv, encWhh, w, lane, base);

    float cstate = 0.f;
    if (tid < 8) {
        g_hbuf[0][base + tid] = 0.f;
        __syncwarp(0xff);
        if (tid == 0) red_rel(&g_cnt[0]);
    }
    __syncthreads();

    for (int t = 0; t < STEPS; t++) {
        if (t == SLEN) load_w(wv, decWhh, w, lane, base);

        if (tid == 0) { while (ld_acq(&g_cnt[t]) < NCTA_REC) {} }
        __syncthreads();
        ((float4*)h_s)[tid] = ((const float4*)g_hbuf[t & 1])[tid];
        __syncthreads();

        unsigned long long acc2[4] = {0ull, 0ull, 0ull, 0ull};
        #pragma unroll
        for (int c = 0; c < 8; c++) {
            const ulonglong2 hv = *(const ulonglong2*)(h_s + lane * 4 + c * 128);
            #pragma unroll
            for (int j = 0; j < 4; j++) {
                ffma2(acc2[j], wv[j][c].x, hv.x);
                ffma2(acc2[j], wv[j][c].y, hv.y);
            }
        }
        float accf[4];
        #pragma unroll
        for (int j = 0; j < 4; j++) {
            float lo, hi; unpack2(acc2[j], lo, hi);
            accf[j] = lo + hi;
        }
        #pragma unroll
        for (int off = 16; off; off >>= 1) {
            #pragma unroll
            for (int j = 0; j < 4; j++)
                accf[j] += __shfl_xor_sync(0xffffffffu, accf[j], off);
        }
        if (lane < 4) gate_s[w * 4 + lane] = accf[lane];
        __syncthreads();

        if (w == 0) {
            const int q = lane >> 3, u = lane & 7;
            const float val = gate_s[lane] + gsl[t * GSL_STRIDE + lane];
            const float act = (q == 2) ? tanh_hw(val) : sig_hw(val);
            const float iv = __shfl_sync(0xffffffffu, act, u);
            const float fv = __shfl_sync(0xffffffffu, act, u + 8);
            const float gv = __shfl_sync(0xffffffffu, act, u + 16);
            const float ov = __shfl_sync(0xffffffffu, act, u + 24);
            if (lane < 8) {
                cstate = fv * cstate + iv * gv;
                const float hh = ov * tanh_hw(cstate);
                g_hbuf[(t + 1) & 1][base + lane] = hh;
                if (t >= SLEN) g_Hbf[(size_t)(t - SLEN) * HD + base + lane] = __float2bfloat16(hh);
            }
            __syncwarp();
            if (lane == 0) red_rel(&g_cnt[t + 1]);
        }
    }
}

// ---------------- 5) logits = H @ linW^T + lin_b  (smem-staged, ldmatrix) ----------------
// Tile: BM=128 (vocab rows), BN=64 (tokens), BK=64. 8 warps, warp w owns rows
// bm+16w..+15. Staging via coalesced uint4; fragments via ldmatrix.x4 from
// padded smem (LPAD=72 bf16 rows -> conflict-free).
__global__ void __launch_bounds__(256) logits_mma(const float* __restrict__ lin_b,
                                                  float* __restrict__ out) {
    __shared__ __nv_bfloat16 sA[128 * LPAD];   // 18.4 KB
    __shared__ __nv_bfloat16 sB[64 * LPAD];    // 9.2 KB

    const int tid = threadIdx.x;
    const int w = tid >> 5, lane = tid & 31;
    const int group = lane >> 2, tig = lane & 3;
    const size_t bm = (size_t)blockIdx.x * 128;
    const int bn = blockIdx.y * 64;

    float acc[8][4];
    #pragma unroll
    for (int nf = 0; nf < 8; nf++)
        #pragma unroll
        for (int q = 0; q < 4; q++) acc[nf][q] = 0.f;

    // ldmatrix lane-address components (computed once)
    const int mi = lane >> 3, r8 = lane & 7;
    // A x4: m0 rows +0..7 col 0 | m1 rows +8..15 col 0 | m2 rows +0..7 col 8 | m3 rows +8..15 col 8
    const int a_row = 16 * w + r8 + ((mi & 1) ? 8 : 0);
    const int a_col = (mi & 2) ? 8 : 0;

    for (int k0 = 0; k0 < HD; k0 += 64) {
        // stage A: 128 rows x 64 cols (8 uint4/row), 4 uint4 per thread
        #pragma unroll
        for (int i = tid; i < 128 * 8; i += 256) {
            const int row = i >> 3, c = i & 7;
            *(uint4*)&sA[row * LPAD + c * 8] =
                *(const uint4*)&g_linw_bf[(bm + row) * HD + k0 + c * 8];
        }
        // stage B: 64 rows x 64 cols, 2 uint4 per thread
        #pragma unroll
        for (int i = tid; i < 64 * 8; i += 256) {
            const int row = i >> 3, c = i & 7;
            *(uint4*)&sB[row * LPAD + c * 8] =
                *(const uint4*)&g_Hbf[(size_t)(bn + row) * HD + k0 + c * 8];
        }
        __syncthreads();

        #pragma unroll
        for (int kk = 0; kk < 64; kk += 16) {
            unsigned a[4];
            ldsm_x4(a[0], a[1], a[2], a[3],
                    smem_u32(&sA[a_row * LPAD + kk + a_col]));
            unsigned b[8][2];
            #pragma unroll
            for (int p = 0; p < 4; p++) {
                // x4: m0=(nf0,kk) m1=(nf0,kk+8) m2=(nf1,kk) m3=(nf1,kk+8)
                const int b_row = (2 * p + (mi >> 1)) * 8 + r8;
                const int b_col = kk + ((mi & 1) ? 8 : 0);
                ldsm_x4(b[2 * p][0], b[2 * p][1], b[2 * p + 1][0], b[2 * p + 1][1],
                        smem_u32(&sB[b_row * LPAD + b_col]));
            }
            #pragma unroll
            for (int nf = 0; nf < 8; nf++)
                mma_bf16(acc[nf], a[0], a[1], a[2], a[3], b[nf][0], b[nf][1]);
        }
        __syncthreads();
    }

    const size_t m0 = bm + 16 * w + group;
    const float bias0 = lin_b[m0];
    const float bias8 = lin_b[m0 + 8];
    #pragma unroll
    for (int nf = 0; nf < 8; nf++) {
        const int n = bn + nf * 8 + 2 * tig;
        out[(size_t)n * VOUT + m0]           = acc[nf][0] + bias0;
        out[(size_t)(n + 1) * VOUT + m0]     = acc[nf][1] + bias0;
        out[(size_t)n * VOUT + m0 + 8]       = acc[nf][2] + bias8;
        out[(size_t)(n + 1) * VOUT + m0 + 8] = acc[nf][3] + bias8;
    }
}

// ---------------- 6) in-place row log_softmax (online, float4, 512 thr) ----------------
__global__ void __launch_bounds__(512) logsoftmax_kernel(float* __restrict__ out) {
    const int t = blockIdx.x;
    float* row = out + (size_t)t * VOUT;
    const int tid = threadIdx.x;
    __shared__ float smx[16], ssm[16];
    __shared__ float sbcast;

    float4* r4 = (float4*)row;
    float m = -3.4e38f, s = 0.f;
    for (int i = tid; i < VOUT / 4; i += 512) {
        const float4 v = r4[i];
        const float vm = fmaxf(fmaxf(v.x, v.y), fmaxf(v.z, v.w));
        const float nm = fmaxf(m, vm);
        s = s * __expf(m - nm) + __expf(v.x - nm) + __expf(v.y - nm)
                               + __expf(v.z - nm) + __expf(v.w - nm);
        m = nm;
    }
    #pragma unroll
    for (int o = 16; o; o >>= 1) {
        const float mo = __shfl_xor_sync(0xffffffffu, m, o);
        const float so = __shfl_xor_sync(0xffffffffu, s, o);
        const float nm = fmaxf(m, mo);
        s = s * __expf(m - nm) + so * __expf(mo - nm);
        m = nm;
    }
    if ((tid & 31) == 0) { smx[tid >> 5] = m; ssm[tid >> 5] = s; }
    __syncthreads();
    if (tid == 0) {
        float M = smx[0], S = ssm[0];
        for (int wq = 1; wq < 16; wq++) {
            const float nm = fmaxf(M, smx[wq]);
            S = S * __expf(M - nm) + ssm[wq] * __expf(smx[wq] - nm);
            M = nm;
        }
        sbcast = M + logf(S);
    }
    __syncthreads();
    const float lse = sbcast;
    for (int i = tid; i < VOUT / 4; i += 512) {
        float4 v = r4[i];
        v.x -= lse; v.y -= lse; v.z -= lse; v.w -= lse;
        r4[i] = v;
    }
}

// ---------------- launch ----------------
extern "C" void kernel_launch(void* const* d_in, const int* in_sizes, int n_in,
                              void* d_out, int out_size) {
    const int*   src     = (const int*)d_in[0];
    const int*   trg     = (const int*)d_in[1];
    const int*   start   = (const int*)d_in[2];
    const float* enc_emb = (const float*)d_in[3];
    const float* enc_Wih = (const float*)d_in[4];
    const float* enc_Whh = (const float*)d_in[5];
    const float* enc_bih = (const float*)d_in[6];
    const float* enc_bhh = (const float*)d_in[7];
    const float* dec_emb = (const float*)d_in[8];
    const float* dec_Wih = (const float*)d_in[9];
    const float* dec_Whh = (const float*)d_in[10];
    const float* dec_bih = (const float*)d_in[11];
    const float* dec_bhh = (const float*)d_in[12];
    const float* lin_W   = (const float*)d_in[13];
    const float* lin_b   = (const float*)d_in[14];
    float* out = (float*)d_out;

    prep_kernel<<<STEPS + 128, 256>>>(src, trg, start, enc_emb, dec_emb,
                                      enc_Wih, dec_Wih);

    dim3 gwx(G4 / 128, SLEN / 64, 2);
    wx_mma<<<gwx, 128>>>(enc_bih, enc_bhh, dec_bih, dec_bhh);

    const int REC_SMEM = (STEPS * GSL_STRIDE + HD + 32) * 4;   // ~71.8 KB
    cudaFuncSetAttribute(rec_kernel, cudaFuncAttributeMaxDynamicSharedMemorySize, REC_SMEM);
    rec_kernel<<<NCTA_TOTAL, 256, REC_SMEM>>>(enc_Whh, dec_Whh, lin_W);

    dim3 gl(VOUT / 128, TLEN / 64);
    logits_mma<<<gl, 256>>>(lin_b, out);

    logsoftmax_kernel<<<TLEN, 512>>>(out);
}